// round 7
// baseline (speedup 1.0000x reference)
#include <cuda_runtime.h>
#include <math.h>
#include <stdint.h>

#define B_ 8
#define C_ 192
#define H_ 128
#define W_ 128
#define HW_ 16384
#define HEADS_ 8
#define CPH_ 24
#define TEMP_INV 100.0f
#define EPS_ 1e-12f

#define NPIX_ (B_ * HW_)
#define NTILES_ (NPIX_ / 128)
#define TILE_ELEMS (128 * C_)

// ---------------- scratch ----------------
__device__ float g_o1[(size_t)B_ * C_ * HW_];
__device__ float g_o2[(size_t)B_ * C_ * HW_];
__device__ float g_o1t[(size_t)B_ * C_ * HW_];
__device__ float g_o2t[(size_t)B_ * C_ * HW_];
__device__ float g_fus[(size_t)B_ * C_ * HW_];
__device__ float g_cl[(size_t)NPIX_ * C_];
__device__ float g_attn1[(size_t)B_ * HEADS_ * HW_];
__device__ float g_attn2[(size_t)B_ * HEADS_ * HW_];
__device__ float g_n1h[B_ * HEADS_ * H_];
__device__ float g_n2h[B_ * HEADS_ * H_];
__device__ float g_n1w[B_ * HEADS_ * W_];
__device__ float g_n2w[B_ * HEADS_ * W_];

__device__ __forceinline__ float to_tf32(float x) {
    uint32_t u; asm("cvt.rna.tf32.f32 %0, %1;" : "=r"(u) : "f"(x));
    return __uint_as_float(u);
}
__device__ __forceinline__ float4 to_tf32_4(float4 v) {
    v.x = to_tf32(v.x); v.y = to_tf32(v.y); v.z = to_tf32(v.z); v.w = to_tf32(v.w);
    return v;
}

__device__ __forceinline__ void mma_tf32(float* c, const uint32_t* a, const uint32_t* b) {
    asm volatile(
        "mma.sync.aligned.m16n8k8.row.col.f32.tf32.tf32.f32 "
        "{%0,%1,%2,%3}, {%4,%5,%6,%7}, {%8,%9}, {%0,%1,%2,%3};"
        : "+f"(c[0]), "+f"(c[1]), "+f"(c[2]), "+f"(c[3])
        : "r"(a[0]), "r"(a[1]), "r"(a[2]), "r"(a[3]), "r"(b[0]), "r"(b[1]));
}

__device__ __forceinline__ void cpa16(uint32_t s, const void* g) {
    asm volatile("cp.async.cg.shared.global [%0], [%1], 16;" :: "r"(s), "l"(g));
}
#define CP_COMMIT() asm volatile("cp.async.commit_group;" ::: "memory")
#define CP_WAIT1()  asm volatile("cp.async.wait_group 1;" ::: "memory")
#define CP_WAIT0()  asm volatile("cp.async.wait_group 0;" ::: "memory")

// ---------------- transpose: channel-first -> channel-last, tf32-rounded ----
__global__ __launch_bounds__(256) void transpose_cf_cl_kernel(
    const float* __restrict__ in, float* __restrict__ out)
{
    __shared__ float t[32][33];
    const int b = blockIdx.z;
    const int p0 = blockIdx.x * 32;
    const int c0 = blockIdx.y * 32;
    const int tx = threadIdx.x, ty = threadIdx.y;
    const float* ib = in + (size_t)b * C_ * HW_;
    float* ob = out + (size_t)b * HW_ * C_;
#pragma unroll
    for (int i = ty; i < 32; i += 8)
        t[i][tx] = ib[(size_t)(c0 + i) * HW_ + p0 + tx];
    __syncthreads();
#pragma unroll
    for (int i = ty; i < 32; i += 8)
        ob[(size_t)(p0 + i) * C_ + c0 + tx] = to_tf32(t[tx][i]);
}

// ---------------- repack: per (b,c) [y][x] -> [x][y] ----------------
__global__ __launch_bounds__(256) void repack_kernel(
    const float* __restrict__ in, float* __restrict__ out)
{
    __shared__ float t[32][33];
    const int c = blockIdx.y, b = blockIdx.z;
    const int x0 = (blockIdx.x & 3) * 32, y0 = (blockIdx.x >> 2) * 32;
    const int tx = threadIdx.x, ty = threadIdx.y;
    const float* ib = in + ((size_t)b * C_ + c) * HW_;
    float* ob = out + ((size_t)b * C_ + c) * HW_;
#pragma unroll
    for (int i = ty; i < 32; i += 8)
        t[i][tx] = ib[(y0 + i) * 128 + x0 + tx];
    __syncthreads();
#pragma unroll
    for (int i = ty; i < 32; i += 8)
        ob[(x0 + i) * 128 + y0 + tx] = t[tx][i];
}

// ---------------- conv1x1 via mma.sync tf32, 512 thr, double-buffered ----------------
// flags: bit0 gelu, bit1 channel-last out (tf32-rounded), bit3 round channel-first out
#define SAS 36
#define CONV_ABUF (128 * SAS)
#define CONV_WBUF (192 * SAS)
#define CONV_SMEM_FLOATS (128 * 196)
#define SMEM_BYTES (CONV_SMEM_FLOATS * 4)

__global__ __launch_bounds__(512, 1) void conv_mma_kernel(
    const float* __restrict__ Acl, const float* __restrict__ Wt,
    const float* __restrict__ bias, float* __restrict__ out,
    int flags, const float* __restrict__ r1, const float* __restrict__ r2)
{
    extern __shared__ float sm[];
    const int tid = threadIdx.x;
    const int lane = tid & 31;
    const int g = lane >> 2;
    const int tig = lane & 3;
    const int wid = tid >> 5;
    const int mbase = (wid & 3) * 32;
    const int nbase = (wid >> 2) * 48;
    const int t = blockIdx.x;
    const float* Arow = Acl + (size_t)t * TILE_ELEMS;

    float c[2][6][4];
#pragma unroll
    for (int mt = 0; mt < 2; mt++)
#pragma unroll
        for (int nt = 0; nt < 6; nt++)
#pragma unroll
            for (int r = 0; r < 4; r++) c[mt][nt][r] = 0.f;

    float4 pa[2], pw[3];
#pragma unroll
    for (int r = 0; r < 2; r++) {
        int f = tid + 512 * r;
        int pix = f >> 3, c4 = f & 7;
        pa[r] = *(const float4*)(Arow + (size_t)pix * C_ + c4 * 4);
    }
#pragma unroll
    for (int r = 0; r < 3; r++) {
        int f = tid + 512 * r;
        int o = f >> 3, c4 = f & 7;
        pw[r] = *(const float4*)(Wt + (size_t)o * C_ + c4 * 4);
    }

    for (int kc = 0; kc < 6; kc++) {
        float* dA = sm + (kc & 1) * CONV_ABUF;
        float* dW = sm + 2 * CONV_ABUF + (kc & 1) * CONV_WBUF;
#pragma unroll
        for (int r = 0; r < 2; r++) {
            int f = tid + 512 * r;
            int pix = f >> 3, c4 = f & 7;
            *(float4*)&dA[pix * SAS + c4 * 4] = pa[r];
        }
#pragma unroll
        for (int r = 0; r < 3; r++) {
            int f = tid + 512 * r;
            int o = f >> 3, c4 = f & 7;
            *(float4*)&dW[o * SAS + c4 * 4] = to_tf32_4(pw[r]);
        }
        __syncthreads();
        if (kc < 5) {
            int ko = (kc + 1) * 32;
#pragma unroll
            for (int r = 0; r < 2; r++) {
                int f = tid + 512 * r;
                int pix = f >> 3, c4 = f & 7;
                pa[r] = *(const float4*)(Arow + (size_t)pix * C_ + ko + c4 * 4);
            }
#pragma unroll
            for (int r = 0; r < 3; r++) {
                int f = tid + 512 * r;
                int o = f >> 3, c4 = f & 7;
                pw[r] = *(const float4*)(Wt + (size_t)o * C_ + ko + c4 * 4);
            }
        }
#pragma unroll
        for (int kk = 0; kk < 4; kk++) {
            const int k0 = kk * 8 + tig;
            uint32_t a[2][4], b[6][2];
#pragma unroll
            for (int mt = 0; mt < 2; mt++) {
                int row = mbase + mt * 16 + g;
                a[mt][0] = __float_as_uint(dA[row * SAS + k0]);
                a[mt][1] = __float_as_uint(dA[(row + 8) * SAS + k0]);
                a[mt][2] = __float_as_uint(dA[row * SAS + k0 + 4]);
                a[mt][3] = __float_as_uint(dA[(row + 8) * SAS + k0 + 4]);
            }
#pragma unroll
            for (int nt = 0; nt < 6; nt++) {
                int col = nbase + nt * 8 + g;
                b[nt][0] = __float_as_uint(dW[col * SAS + k0]);
                b[nt][1] = __float_as_uint(dW[col * SAS + k0 + 4]);
            }
#pragma unroll
            for (int mt = 0; mt < 2; mt++)
#pragma unroll
                for (int nt = 0; nt < 6; nt++)
                    mma_tf32(c[mt][nt], a[mt], b[nt]);
        }
    }
    __syncthreads();

    const int gelu = flags & 1;
    const int rnd = flags & 8;
    float bv[6][2];
#pragma unroll
    for (int nt = 0; nt < 6; nt++) {
        int o = nbase + nt * 8 + 2 * tig;
        bv[nt][0] = __ldg(&bias[o]);
        bv[nt][1] = __ldg(&bias[o + 1]);
    }

    if (flags & 2) {
        float* sO = sm;
#pragma unroll
        for (int mt = 0; mt < 2; mt++) {
            int row0 = mbase + mt * 16 + g;
#pragma unroll
            for (int nt = 0; nt < 6; nt++) {
                int o = nbase + nt * 8 + 2 * tig;
#pragma unroll
                for (int half = 0; half < 2; half++) {
                    int row = row0 + half * 8;
                    float v0 = c[mt][nt][half * 2 + 0] + bv[nt][0];
                    float v1 = c[mt][nt][half * 2 + 1] + bv[nt][1];
                    if (gelu) {
                        v0 = 0.5f * v0 * (1.0f + erff(v0 * 0.70710678118654752f));
                        v1 = 0.5f * v1 * (1.0f + erff(v1 * 0.70710678118654752f));
                    }
                    float2 w = {to_tf32(v0), to_tf32(v1)};
                    *(float2*)&sO[row * 196 + o] = w;
                }
            }
        }
        __syncthreads();
        float* ob = out + (size_t)t * TILE_ELEMS;
#pragma unroll
        for (int r = 0; r < 12; r++) {
            int f = tid + 512 * r;
            int pix = f / 48, c4 = f % 48;
            *(float4*)(ob + (size_t)pix * C_ + c4 * 4) = *(float4*)&sO[pix * 196 + c4 * 4];
        }
    } else {
        const int pg0 = t << 7;
        const int b = pg0 >> 14;
        const int p0 = pg0 & (HW_ - 1);
#pragma unroll
        for (int mt = 0; mt < 2; mt++) {
            int row0 = mbase + mt * 16 + g;
#pragma unroll
            for (int nt = 0; nt < 6; nt++) {
                int o = nbase + nt * 8 + 2 * tig;
#pragma unroll
                for (int half = 0; half < 2; half++) {
                    int row = row0 + half * 8;
#pragma unroll
                    for (int cc = 0; cc < 2; cc++) {
                        float v = c[mt][nt][half * 2 + cc] + bv[nt][cc];
                        if (gelu) v = 0.5f * v * (1.0f + erff(v * 0.70710678118654752f));
                        size_t idx = ((size_t)(b * C_ + o + cc) << 14) + p0 + row;
                        if (r1) v += __ldg(&r1[idx]) + __ldg(&r2[idx]);
                        if (rnd) v = to_tf32(v);
                        out[idx] = v;
                    }
                }
            }
        }
    }
}

// ---------------- norms ----------------
__global__ __launch_bounds__(256) void norm_kernel(
    const float* __restrict__ o1, const float* __restrict__ o2,
    float* __restrict__ n1h, float* __restrict__ n1w,
    float* __restrict__ n2h, float* __restrict__ n2w)
{
    const int bh = blockIdx.x;
    const int src = blockIdx.y;
    const int tid = threadIdx.x;
    const float* base = (src ? o2 : o1) + ((size_t)(bh >> 3) * C_ + (bh & 7) * CPH_) * HW_;

    __shared__ float sRow[128];
    __shared__ float sColA[256];
    if (tid < 128) sRow[tid] = 0.f;
    __syncthreads();

    float colAcc = 0.f;
    for (int idx = tid; idx < CPH_ * HW_; idx += 256) {
        float v = base[idx];
        v *= v;
        colAcc += v;
        float rv = v;
#pragma unroll
        for (int s = 16; s >= 1; s >>= 1) rv += __shfl_xor_sync(0xffffffffu, rv, s);
        if ((tid & 31) == 0) atomicAdd(&sRow[(idx >> 7) & 127], rv);
    }
    sColA[tid] = colAcc;
    __syncthreads();
    if (tid < 128) {
        float cs = sColA[tid] + sColA[tid + 128];
        float rs = sRow[tid];
        if (src) { n2h[bh * 128 + tid] = sqrtf(rs); n2w[bh * 128 + tid] = sqrtf(cs); }
        else     { n1h[bh * 128 + tid] = sqrtf(rs); n1w[bh * 128 + tid] = sqrtf(cs); }
    }
}

// ---------------- shared constants for attn/av (256 thr, M-split 64) ----------------
#define PAS 68
#define AB_A (64 * PAS)            // 4352 floats
#define AB_B (128 * PAS)           // 8704 floats
#define PBUF (AB_A + AB_B)         // 13056 floats
#define PIPE_SMEM_BYTES (2 * PBUF * 4)   // 104448 -> 2 CTAs/SM

// stage one K-chunk of 64: A half-tile (64 x 64), B full (128 x 64), via cp.async
#define PIPE_STAGE(sbuf32, Ap, Bp) do {                                          \
    _Pragma("unroll")                                                            \
    for (int r = 0; r < 4; r++) {                                                \
        int f = tid + 256 * r;                                                   \
        int row = f >> 4, c4 = f & 15;                                           \
        cpa16((sbuf32) + (row * PAS + c4 * 4) * 4, (Ap) + row * 128 + c4 * 4);   \
    }                                                                            \
    _Pragma("unroll")                                                            \
    for (int r = 0; r < 8; r++) {                                                \
        int f = tid + 256 * r;                                                   \
        int row = f >> 4, c4 = f & 15;                                           \
        cpa16((sbuf32) + (AB_A + row * PAS + c4 * 4) * 4, (Bp) + row * 128 + c4 * 4); \
    }                                                                            \
    CP_COMMIT();                                                                 \
} while (0)

// MMA over one staged chunk (K=64): warp tile 32x32, acc[2][4][4]
#define PIPE_MMA(dA, dB, ACC) do {                                               \
    _Pragma("unroll")                                                            \
    for (int k4 = 0; k4 < 8; k4++) {                                             \
        const int k0 = k4 * 8 + tig;                                             \
        uint32_t a[2][4], bf[4][2];                                              \
        _Pragma("unroll")                                                        \
        for (int mt = 0; mt < 2; mt++) {                                         \
            int row = mbase + mt * 16 + g;                                       \
            a[mt][0] = __float_as_uint((dA)[row * PAS + k0]);                    \
            a[mt][1] = __float_as_uint((dA)[(row + 8) * PAS + k0]);              \
            a[mt][2] = __float_as_uint((dA)[row * PAS + k0 + 4]);                \
            a[mt][3] = __float_as_uint((dA)[(row + 8) * PAS + k0 + 4]);          \
        }                                                                        \
        _Pragma("unroll")                                                        \
        for (int nt = 0; nt < 4; nt++) {                                         \
            int col = nbase + nt * 8 + g;                                        \
            bf[nt][0] = __float_as_uint((dB)[col * PAS + k0]);                   \
            bf[nt][1] = __float_as_uint((dB)[col * PAS + k0 + 4]);               \
        }                                                                        \
        _Pragma("unroll")                                                        \
        for (int mt = 0; mt < 2; mt++)                                           \
            _Pragma("unroll")                                                    \
            for (int nt = 0; nt < 4; nt++)                                       \
                mma_tf32(ACC[mt][nt], a[mt], bf[nt]);                            \
    }                                                                            \
} while (0)

// ---------------- attention: 256 thr, M-split, cp.async pipeline ----------------
__global__ __launch_bounds__(256, 2) void attn_mma_kernel(
    const float* __restrict__ o1, const float* __restrict__ o2,
    const float* __restrict__ o1t, const float* __restrict__ o2t,
    const float* __restrict__ n1h, const float* __restrict__ n2h,
    const float* __restrict__ n1w, const float* __restrict__ n2w,
    const float* __restrict__ pbh, const float* __restrict__ pbw,
    float* __restrict__ attn1, float* __restrict__ attn2)
{
    extern __shared__ float sm[];
    const uint32_t sbase = (uint32_t)__cvta_generic_to_shared(sm);
    const int bh = blockIdx.x;
    const int mode = blockIdx.y;
    const int mh = blockIdx.z;
    const int hd = bh & 7, b = bh >> 3;
    const int tid = threadIdx.x;
    const int lane = tid & 31, g = lane >> 2, tig = lane & 3;
    const int wid = tid >> 5;
    const int mbase = (wid & 1) * 32;
    const int nbase = (wid >> 1) * 32;
    const int mh64 = mh * 64;
    const float* Abase = ((mode ? o1t : o2) + ((size_t)b * C_ + hd * CPH_) * HW_) + mh64 * 128;
    const float* Bbase = (mode ? o2t : o1) + ((size_t)b * C_ + hd * CPH_) * HW_;

    float acc[2][4][4];
#pragma unroll
    for (int mt = 0; mt < 2; mt++)
#pragma unroll
        for (int nt = 0; nt < 4; nt++)
#pragma unroll
            for (int e = 0; e < 4; e++) acc[mt][nt][e] = 0.f;

    // pipeline: 48 chunks of K=64
    {
        const float* Ap0 = Abase;
        const float* Bp0 = Bbase;
        PIPE_STAGE(sbase, Ap0, Bp0);
    }
    for (int kc = 0; kc < 48; kc++) {
        if (kc < 47) {
            int kn = kc + 1;
            const float* Ap = Abase + (kn >> 1) * HW_ + (kn & 1) * 64;
            const float* Bp = Bbase + (kn >> 1) * HW_ + (kn & 1) * 64;
            uint32_t sbuf = sbase + ((kn & 1) * PBUF) * 4;
            PIPE_STAGE(sbuf, Ap, Bp);
            CP_WAIT1();
        } else {
            CP_WAIT0();
        }
        __syncthreads();
        const float* dA = sm + (kc & 1) * PBUF;
        const float* dB = dA + AB_A;
        PIPE_MMA(dA, dB, acc);
        __syncthreads();
    }

    // scale + bias -> logits in smem (rows local 0..63)
    const float* nI = mode ? n1w : n2h;
    const float* nJ = mode ? n2w : n1h;
    const float bias = mode ? __ldg(&pbw[hd]) : __ldg(&pbh[hd]);
    float rinv[4], cinv[8];
#pragma unroll
    for (int mt = 0; mt < 2; mt++)
#pragma unroll
        for (int half = 0; half < 2; half++) {
            int row = mbase + mt * 16 + g + half * 8;
            rinv[mt * 2 + half] = TEMP_INV / fmaxf(__ldg(&nI[bh * 128 + mh64 + row]), EPS_);
        }
#pragma unroll
    for (int nt = 0; nt < 4; nt++)
#pragma unroll
        for (int cc = 0; cc < 2; cc++) {
            int col = nbase + nt * 8 + 2 * tig + cc;
            cinv[nt * 2 + cc] = 1.f / fmaxf(__ldg(&nJ[bh * 128 + col]), EPS_);
        }
    float* sc = sm;   // 64 x 132 logits
#pragma unroll
    for (int mt = 0; mt < 2; mt++)
#pragma unroll
        for (int half = 0; half < 2; half++) {
            int row = mbase + mt * 16 + g + half * 8;
            float ri = rinv[mt * 2 + half];
#pragma unroll
            for (int nt = 0; nt < 4; nt++) {
                int col = nbase + nt * 8 + 2 * tig;
                float2 v;
                v.x = acc[mt][nt][half * 2 + 0] * (ri * cinv[nt * 2 + 0]) + bias;
                v.y = acc[mt][nt][half * 2 + 1] * (ri * cinv[nt * 2 + 1]) + bias;
                *(float2*)&sc[row * 132 + col] = v;
            }
        }
    __syncthreads();

    float* outp = (mode ? attn2 : attn1) + (size_t)bh * HW_ + mh64 * 128;
    for (int r = wid; r < 64; r += 8) {
        float4 v = *(float4*)&sc[r * 132 + lane * 4];
        float m = fmaxf(fmaxf(v.x, v.y), fmaxf(v.z, v.w));
#pragma unroll
        for (int s = 16; s >= 1; s >>= 1) m = fmaxf(m, __shfl_xor_sync(0xffffffffu, m, s));
        v.x = __expf(v.x - m); v.y = __expf(v.y - m);
        v.z = __expf(v.z - m); v.w = __expf(v.w - m);
        float su = v.x + v.y + v.z + v.w;
#pragma unroll
        for (int s = 16; s >= 1; s >>= 1) su += __shfl_xor_sync(0xffffffffu, su, s);
        float inv = 1.f / su;
        v.x *= inv; v.y *= inv; v.z *= inv; v.w *= inv;
        *(float4*)&outp[r * 128 + lane * 4] = to_tf32_4(v);
    }
}

// ---------------- AV + q-residual + gated fusion: 256 thr, M-split, cp.async ----------------
__global__ __launch_bounds__(256, 2) void av_mma_kernel(
    const float* __restrict__ o1, const float* __restrict__ o2,
    const float* __restrict__ o1t,
    const float* __restrict__ attn1, const float* __restrict__ attn2,
    const float* __restrict__ n2h, const float* __restrict__ n1w,
    const float* __restrict__ gate, float* __restrict__ fus)
{
    extern __shared__ float sm[];
    const uint32_t sbase = (uint32_t)__cvta_generic_to_shared(sm);
    const int ch = blockIdx.x, b = blockIdx.y;
    const int mh = blockIdx.z;
    const int hd = ch / CPH_;
    const int bh = b * 8 + hd;
    const int tid = threadIdx.x;
    const int lane = tid & 31, g = lane >> 2, tig = lane & 3;
    const int wid = tid >> 5;
    const int mbase = (wid & 1) * 32;
    const int nbase = (wid >> 1) * 32;
    const int mh64 = mh * 64;

    const float* A1 = attn1 + (size_t)bh * HW_ + mh64 * 128;   // [m][k]
    const float* B1 = o1t + ((size_t)b * C_ + ch) * HW_;       // [n=x][k=j]
    const float* A2 = o2 + ((size_t)b * C_ + ch) * HW_ + mh64 * 128;  // [m=y][k=j]
    const float* B2 = attn2 + (size_t)bh * HW_;                // [n=x][k=j]
    const float* S1 = o1 + ((size_t)b * C_ + ch) * HW_;
    const float* S2 = o2 + ((size_t)b * C_ + ch) * HW_;

    float acc1[2][4][4], acc2[2][4][4];
#pragma unroll
    for (int mt = 0; mt < 2; mt++)
#pragma unroll
        for (int nt = 0; nt < 4; nt++)
#pragma unroll
            for (int e = 0; e < 4; e++) { acc1[mt][nt][e] = 0.f; acc2[mt][nt][e] = 0.f; }

    const uint32_t sb0 = sbase;
    const uint32_t sb1 = sbase + PBUF * 4;
    const float* dA0 = sm;
    const float* dB0 = sm + AB_A;
    const float* dA1 = sm + PBUF;
    const float* dB1 = sm + PBUF + AB_A;

    // chunks: (G1,k0)->b0, (G1,k1)->b1, (G2,k0)->b0, (G2,k1)->b1
    PIPE_STAGE(sb0, A1, B1);
    PIPE_STAGE(sb1, A1 + 64, B1 + 64);
    CP_WAIT1(); __syncthreads();
    PIPE_MMA(dA0, dB0, acc1);
    __syncthreads();
    PIPE_STAGE(sb0, A2, B2);
    CP_WAIT1(); __syncthreads();
    PIPE_MMA(dA1, dB1, acc1);
    __syncthreads();
    PIPE_STAGE(sb1, A2 + 64, B2 + 64);
    CP_WAIT1(); __syncthreads();
    PIPE_MMA(dA0, dB0, acc2);
    CP_WAIT0(); __syncthreads();
    PIPE_MMA(dA1, dB1, acc2);

    const float gg = 1.f / (1.f + expf(-__ldg(&gate[0])));
    float invy[4], invx[8];
#pragma unroll
    for (int mt = 0; mt < 2; mt++)
#pragma unroll
        for (int half = 0; half < 2; half++) {
            int row = mbase + mt * 16 + g + half * 8;
            invy[mt * 2 + half] = 1.f / fmaxf(__ldg(&n2h[bh * 128 + mh64 + row]), EPS_);
        }
#pragma unroll
    for (int nt = 0; nt < 4; nt++)
#pragma unroll
        for (int cc = 0; cc < 2; cc++) {
            int col = nbase + nt * 8 + 2 * tig + cc;
            invx[nt * 2 + cc] = 1.f / fmaxf(__ldg(&n1w[bh * 128 + col]), EPS_);
        }

    float* fout = fus + ((size_t)b * C_ + ch) * HW_;
#pragma unroll
    for (int mt = 0; mt < 2; mt++)
#pragma unroll
        for (int half = 0; half < 2; half++) {
            int rl = mbase + mt * 16 + g + half * 8;
            int row = mh64 + rl;
            float iy = invy[mt * 2 + half];
#pragma unroll
            for (int nt = 0; nt < 4; nt++) {
                int col = nbase + nt * 8 + 2 * tig;
                float2 s1v = *(const float2*)(S1 + row * 128 + col);
                float2 s2v = *(const float2*)(S2 + row * 128 + col);
                float2 o;
                o.x = gg * (acc1[mt][nt][half * 2 + 0] + s2v.x * iy)
                    + (1.f - gg) * (acc2[mt][nt][half * 2 + 0] + s1v.x * invx[nt * 2 + 0]);
                o.y = gg * (acc1[mt][nt][half * 2 + 1] + s2v.y * iy)
                    + (1.f - gg) * (acc2[mt][nt][half * 2 + 1] + s1v.y * invx[nt * 2 + 1]);
                *(float2*)(fout + row * 128 + col) = o;
            }
        }
}

// ---------------- host launcher ----------------
extern "C" void kernel_launch(void* const* d_in, const int* in_sizes, int n_in,
                              void* d_out, int out_size)
{
    const float* x1  = (const float*)d_in[0];
    const float* x2  = (const float*)d_in[1];
    const float* Wp  = (const float*)d_in[2];
    const float* bp  = (const float*)d_in[3];
    const float* gate= (const float*)d_in[4];
    const float* pbh = (const float*)d_in[5];
    const float* pbw = (const float*)d_in[6];
    const float* Wm1 = (const float*)d_in[7];
    const float* bm1 = (const float*)d_in[8];
    const float* Wm2 = (const float*)d_in[9];
    const float* bm2 = (const float*)d_in[10];
    float* out = (float*)d_out;

    float *p_o1, *p_o2, *p_o1t, *p_o2t, *p_fus, *p_cl, *p_a1, *p_a2;
    float *p_n1h, *p_n2h, *p_n1w, *p_n2w;
    cudaGetSymbolAddress((void**)&p_o1, g_o1);
    cudaGetSymbolAddress((void**)&p_o2, g_o2);
    cudaGetSymbolAddress((void**)&p_o1t, g_o1t);
    cudaGetSymbolAddress((void**)&p_o2t, g_o2t);
    cudaGetSymbolAddress((void**)&p_fus, g_fus);
    cudaGetSymbolAddress((void**)&p_cl, g_cl);
    cudaGetSymbolAddress((void**)&p_a1, g_attn1);
    cudaGetSymbolAddress((void**)&p_a2, g_attn2);
    cudaGetSymbolAddress((void**)&p_n1h, g_n1h);
    cudaGetSymbolAddress((void**)&p_n2h, g_n2h);
    cudaGetSymbolAddress((void**)&p_n1w, g_n1w);
    cudaGetSymbolAddress((void**)&p_n2w, g_n2w);

    cudaFuncSetAttribute(conv_mma_kernel, cudaFuncAttributeMaxDynamicSharedMemorySize, SMEM_BYTES);
    cudaFuncSetAttribute(attn_mma_kernel, cudaFuncAttributeMaxDynamicSharedMemorySize, PIPE_SMEM_BYTES);
    cudaFuncSetAttribute(av_mma_kernel, cudaFuncAttributeMaxDynamicSharedMemorySize, PIPE_SMEM_BYTES);

    dim3 tGrid(HW_ / 32, C_ / 32, B_);
    dim3 tBlk(32, 8);
    dim3 rGrid(16, C_, B_);

    // out1 = conv(x1) -> channel-first, tf32-rounded
    transpose_cf_cl_kernel<<<tGrid, tBlk>>>(x1, p_cl);
    conv_mma_kernel<<<NTILES_, 512, SMEM_BYTES>>>(p_cl, Wp, bp, p_o1, 8, nullptr, nullptr);
    transpose_cf_cl_kernel<<<tGrid, tBlk>>>(x2, p_cl);
    conv_mma_kernel<<<NTILES_, 512, SMEM_BYTES>>>(p_cl, Wp, bp, p_o2, 8, nullptr, nullptr);

    norm_kernel<<<dim3(B_ * HEADS_, 2), 256>>>(p_o1, p_o2, p_n1h, p_n1w, p_n2h, p_n2w);
    repack_kernel<<<rGrid, tBlk>>>(p_o1, p_o1t);
    repack_kernel<<<rGrid, tBlk>>>(p_o2, p_o2t);

    attn_mma_kernel<<<dim3(B_ * HEADS_, 2, 2), 256, PIPE_SMEM_BYTES>>>(
        p_o1, p_o2, p_o1t, p_o2t, p_n1h, p_n2h, p_n1w, p_n2w, pbh, pbw, p_a1, p_a2);

    av_mma_kernel<<<dim3(C_, B_, 2), 256, PIPE_SMEM_BYTES>>>(
        p_o1, p_o2, p_o1t, p_a1, p_a2, p_n2h, p_n1w, gate, p_fus);

    // out5 = conv(fusion, W_proj) -> channel-last
    transpose_cf_cl_kernel<<<tGrid, tBlk>>>(p_fus, p_cl);
    conv_mma_kernel<<<NTILES_, 512, SMEM_BYTES>>>(p_cl, Wp, bp, p_o1, 2, nullptr, nullptr);
    conv_mma_kernel<<<NTILES_, 512, SMEM_BYTES>>>(p_o1, Wm1, bm1, p_o2, 3, nullptr, nullptr);
    conv_mma_kernel<<<NTILES_, 512, SMEM_BYTES>>>(p_o2, Wm2, bm2, out, 0, x1, x2);

    (void)in_sizes; (void)n_in; (void)out_size;
}

// round 8
// speedup vs baseline: 1.7488x; 1.7488x over previous
#include <cuda_runtime.h>
#include <math.h>
#include <stdint.h>

#define B_ 8
#define C_ 192
#define H_ 128
#define W_ 128
#define HW_ 16384
#define HEADS_ 8
#define CPH_ 24
#define TEMP_INV 100.0f
#define EPS_ 1e-12f

#define NPIX_ (B_ * HW_)
#define NTILES_ (NPIX_ / 128)
#define TILE_ELEMS (128 * C_)

// ---------------- scratch ----------------
__device__ float g_o1[(size_t)B_ * C_ * HW_];
__device__ float g_o2[(size_t)B_ * C_ * HW_];
__device__ float g_o1t[(size_t)B_ * C_ * HW_];
__device__ float g_o2t[(size_t)B_ * C_ * HW_];
__device__ float g_fus[(size_t)B_ * C_ * HW_];
__device__ float g_cl[(size_t)NPIX_ * C_];
__device__ float g_attn1[(size_t)B_ * HEADS_ * HW_];
__device__ float g_attn2[(size_t)B_ * HEADS_ * HW_];
__device__ float g_n1h[B_ * HEADS_ * H_];
__device__ float g_n2h[B_ * HEADS_ * H_];
__device__ float g_n1w[B_ * HEADS_ * W_];
__device__ float g_n2w[B_ * HEADS_ * W_];

__device__ __forceinline__ float to_tf32(float x) {
    uint32_t u; asm("cvt.rna.tf32.f32 %0, %1;" : "=r"(u) : "f"(x));
    return __uint_as_float(u);
}
__device__ __forceinline__ float4 to_tf32_4(float4 v) {
    v.x = to_tf32(v.x); v.y = to_tf32(v.y); v.z = to_tf32(v.z); v.w = to_tf32(v.w);
    return v;
}

__device__ __forceinline__ void mma_tf32(float* c, const uint32_t* a, const uint32_t* b) {
    asm volatile(
        "mma.sync.aligned.m16n8k8.row.col.f32.tf32.tf32.f32 "
        "{%0,%1,%2,%3}, {%4,%5,%6,%7}, {%8,%9}, {%0,%1,%2,%3};"
        : "+f"(c[0]), "+f"(c[1]), "+f"(c[2]), "+f"(c[3])
        : "r"(a[0]), "r"(a[1]), "r"(a[2]), "r"(a[3]), "r"(b[0]), "r"(b[1]));
}

__device__ __forceinline__ void cpa16(uint32_t s, const void* g) {
    asm volatile("cp.async.cg.shared.global [%0], [%1], 16;" :: "r"(s), "l"(g));
}
#define CP_COMMIT() asm volatile("cp.async.commit_group;" ::: "memory")
#define CP_WAIT1()  asm volatile("cp.async.wait_group 1;" ::: "memory")
#define CP_WAIT0()  asm volatile("cp.async.wait_group 0;" ::: "memory")

// ---------------- transpose: channel-first -> channel-last, tf32-rounded ----
__global__ __launch_bounds__(256) void transpose_cf_cl_kernel(
    const float* __restrict__ in, float* __restrict__ out)
{
    __shared__ float t[32][33];
    const int b = blockIdx.z;
    const int p0 = blockIdx.x * 32;
    const int c0 = blockIdx.y * 32;
    const int tx = threadIdx.x, ty = threadIdx.y;
    const float* ib = in + (size_t)b * C_ * HW_;
    float* ob = out + (size_t)b * HW_ * C_;
#pragma unroll
    for (int i = ty; i < 32; i += 8)
        t[i][tx] = ib[(size_t)(c0 + i) * HW_ + p0 + tx];
    __syncthreads();
#pragma unroll
    for (int i = ty; i < 32; i += 8)
        ob[(size_t)(p0 + i) * C_ + c0 + tx] = to_tf32(t[tx][i]);
}

// ---------------- repack + fused squared-sum norms ----------------
// transpose [y][x] -> [x][y] per (b,c); accumulate row (y) and col (x) squared
// sums per head into rowAcc/colAcc (pre-zeroed; sqrt in finalize).
__global__ __launch_bounds__(256) void repack_norm_kernel(
    const float* __restrict__ in, float* __restrict__ out,
    float* __restrict__ rowAcc, float* __restrict__ colAcc)
{
    __shared__ float t[32][33];
    __shared__ float cpart[8][32];
    const int c = blockIdx.y, b = blockIdx.z;
    const int bh = b * 8 + c / CPH_;
    const int x0 = (blockIdx.x & 3) * 32, y0 = (blockIdx.x >> 2) * 32;
    const int tx = threadIdx.x, ty = threadIdx.y;
    const float* ib = in + ((size_t)b * C_ + c) * HW_;
    float* ob = out + ((size_t)b * C_ + c) * HW_;

    float colLoc = 0.f;
#pragma unroll
    for (int ii = 0; ii < 4; ii++) {
        int i = ty + 8 * ii;
        float v = ib[(y0 + i) * 128 + x0 + tx];
        t[i][tx] = v;
        float sq = v * v;
        colLoc += sq;
        float rs = sq;
#pragma unroll
        for (int s = 16; s >= 1; s >>= 1) rs += __shfl_xor_sync(0xffffffffu, rs, s);
        if (tx == 0) atomicAdd(&rowAcc[bh * 128 + y0 + i], rs);
    }
    cpart[ty][tx] = colLoc;
    __syncthreads();
#pragma unroll
    for (int i = ty; i < 32; i += 8)
        ob[(x0 + i) * 128 + y0 + tx] = t[tx][i];
    if (ty == 0) {
        float s = cpart[0][tx] + cpart[1][tx] + cpart[2][tx] + cpart[3][tx]
                + cpart[4][tx] + cpart[5][tx] + cpart[6][tx] + cpart[7][tx];
        atomicAdd(&colAcc[bh * 128 + x0 + tx], s);
    }
}

__global__ void norm_init_kernel(float* a, float* b, float* c, float* d) {
    int i = blockIdx.x * 256 + threadIdx.x;
    if (i < B_ * HEADS_ * 128) { a[i] = 0.f; b[i] = 0.f; c[i] = 0.f; d[i] = 0.f; }
}
__global__ void norm_fin_kernel(float* a, float* b, float* c, float* d) {
    int i = blockIdx.x * 256 + threadIdx.x;
    if (i < B_ * HEADS_ * 128) {
        a[i] = sqrtf(a[i]); b[i] = sqrtf(b[i]); c[i] = sqrtf(c[i]); d[i] = sqrtf(d[i]);
    }
}

// ---------------- conv1x1 via mma.sync tf32, 512 thr, double-buffered ----------------
// flags: bit0 gelu, bit3 round channel-first out
#define SAS 36
#define CONV_ABUF (128 * SAS)
#define CONV_WBUF (192 * SAS)
#define CONV_SMEM_FLOATS (2 * CONV_ABUF + 2 * CONV_WBUF)
#define SMEM_BYTES (CONV_SMEM_FLOATS * 4)

__global__ __launch_bounds__(512, 1) void conv_mma_kernel(
    const float* __restrict__ Acl, const float* __restrict__ Wt,
    const float* __restrict__ bias, float* __restrict__ out,
    int flags, const float* __restrict__ r1, const float* __restrict__ r2)
{
    extern __shared__ float sm[];
    const int tid = threadIdx.x;
    const int lane = tid & 31;
    const int g = lane >> 2;
    const int tig = lane & 3;
    const int wid = tid >> 5;
    const int mbase = (wid & 3) * 32;
    const int nbase = (wid >> 2) * 48;
    const int t = blockIdx.x;
    const float* Arow = Acl + (size_t)t * TILE_ELEMS;

    float c[2][6][4];
#pragma unroll
    for (int mt = 0; mt < 2; mt++)
#pragma unroll
        for (int nt = 0; nt < 6; nt++)
#pragma unroll
            for (int r = 0; r < 4; r++) c[mt][nt][r] = 0.f;

    float4 pa[2], pw[3];
#pragma unroll
    for (int r = 0; r < 2; r++) {
        int f = tid + 512 * r;
        pa[r] = *(const float4*)(Arow + (size_t)(f >> 3) * C_ + (f & 7) * 4);
    }
#pragma unroll
    for (int r = 0; r < 3; r++) {
        int f = tid + 512 * r;
        pw[r] = *(const float4*)(Wt + (size_t)(f >> 3) * C_ + (f & 7) * 4);
    }

    for (int kc = 0; kc < 6; kc++) {
        float* dA = sm + (kc & 1) * CONV_ABUF;
        float* dW = sm + 2 * CONV_ABUF + (kc & 1) * CONV_WBUF;
#pragma unroll
        for (int r = 0; r < 2; r++) {
            int f = tid + 512 * r;
            *(float4*)&dA[(f >> 3) * SAS + (f & 7) * 4] = pa[r];
        }
#pragma unroll
        for (int r = 0; r < 3; r++) {
            int f = tid + 512 * r;
            *(float4*)&dW[(f >> 3) * SAS + (f & 7) * 4] = to_tf32_4(pw[r]);
        }
        __syncthreads();
        if (kc < 5) {
            int ko = (kc + 1) * 32;
#pragma unroll
            for (int r = 0; r < 2; r++) {
                int f = tid + 512 * r;
                pa[r] = *(const float4*)(Arow + (size_t)(f >> 3) * C_ + ko + (f & 7) * 4);
            }
#pragma unroll
            for (int r = 0; r < 3; r++) {
                int f = tid + 512 * r;
                pw[r] = *(const float4*)(Wt + (size_t)(f >> 3) * C_ + ko + (f & 7) * 4);
            }
        }
#pragma unroll
        for (int kk = 0; kk < 4; kk++) {
            const int k0 = kk * 8 + tig;
            uint32_t a[2][4], b[6][2];
#pragma unroll
            for (int mt = 0; mt < 2; mt++) {
                int row = mbase + mt * 16 + g;
                a[mt][0] = __float_as_uint(dA[row * SAS + k0]);
                a[mt][1] = __float_as_uint(dA[(row + 8) * SAS + k0]);
                a[mt][2] = __float_as_uint(dA[row * SAS + k0 + 4]);
                a[mt][3] = __float_as_uint(dA[(row + 8) * SAS + k0 + 4]);
            }
#pragma unroll
            for (int nt = 0; nt < 6; nt++) {
                int col = nbase + nt * 8 + g;
                b[nt][0] = __float_as_uint(dW[col * SAS + k0]);
                b[nt][1] = __float_as_uint(dW[col * SAS + k0 + 4]);
            }
#pragma unroll
            for (int mt = 0; mt < 2; mt++)
#pragma unroll
                for (int nt = 0; nt < 6; nt++)
                    mma_tf32(c[mt][nt], a[mt], b[nt]);
        }
    }
    __syncthreads();

    const int gelu = flags & 1;
    const int rnd = flags & 8;
    float bv[6][2];
#pragma unroll
    for (int nt = 0; nt < 6; nt++) {
        int o = nbase + nt * 8 + 2 * tig;
        bv[nt][0] = __ldg(&bias[o]);
        bv[nt][1] = __ldg(&bias[o + 1]);
    }

    const int pg0 = t << 7;
    const int b = pg0 >> 14;
    const int p0 = pg0 & (HW_ - 1);
#pragma unroll
    for (int mt = 0; mt < 2; mt++) {
        int row0 = mbase + mt * 16 + g;
#pragma unroll
        for (int nt = 0; nt < 6; nt++) {
            int o = nbase + nt * 8 + 2 * tig;
#pragma unroll
            for (int half = 0; half < 2; half++) {
                int row = row0 + half * 8;
#pragma unroll
                for (int cc = 0; cc < 2; cc++) {
                    float v = c[mt][nt][half * 2 + cc] + bv[nt][cc];
                    if (gelu) v = 0.5f * v * (1.0f + erff(v * 0.70710678118654752f));
                    size_t idx = ((size_t)(b * C_ + o + cc) << 14) + p0 + row;
                    if (r1) v += __ldg(&r1[idx]) + __ldg(&r2[idx]);
                    if (rnd) v = to_tf32(v);
                    out[idx] = v;
                }
            }
        }
    }
}

// ---------------- fused triple conv: conv(Wp) -> gelu(conv(Wm1)) -> conv(Wm2)+x1+x2 ----
// A (fus channel-last, tf32-rounded). Intermediates live in smem (stride 196).
#define C3_SO_STRIDE 196
#define C3_SO_FLOATS (128 * C3_SO_STRIDE)      // 25088
#define C3_W_OFF C3_SO_FLOATS
#define C3_SMEM_FLOATS (C3_SO_FLOATS + 2 * CONV_WBUF)   // 25088 + 13824
#define C3_SMEM_BYTES (C3_SMEM_FLOATS * 4)              // 155648

// mma mainloop with A in smem at given stride (kbase = kc*32)
#define C3_MMALOOP(dApt, astr, kbase, dWpt, ACC) do {                            \
    _Pragma("unroll")                                                            \
    for (int kk = 0; kk < 4; kk++) {                                             \
        const int k0 = kk * 8 + tig;                                             \
        uint32_t a[2][4], bb[6][2];                                              \
        _Pragma("unroll")                                                        \
        for (int mt = 0; mt < 2; mt++) {                                         \
            int row = mbase + mt * 16 + g;                                       \
            a[mt][0] = __float_as_uint((dApt)[row * (astr) + (kbase) + k0]);     \
            a[mt][1] = __float_as_uint((dApt)[(row + 8) * (astr) + (kbase) + k0]); \
            a[mt][2] = __float_as_uint((dApt)[row * (astr) + (kbase) + k0 + 4]); \
            a[mt][3] = __float_as_uint((dApt)[(row + 8) * (astr) + (kbase) + k0 + 4]); \
        }                                                                        \
        _Pragma("unroll")                                                        \
        for (int nt = 0; nt < 6; nt++) {                                         \
            int col = nbase + nt * 8 + g;                                        \
            bb[nt][0] = __float_as_uint((dWpt)[col * SAS + k0]);                 \
            bb[nt][1] = __float_as_uint((dWpt)[col * SAS + k0 + 4]);             \
        }                                                                        \
        _Pragma("unroll")                                                        \
        for (int mt = 0; mt < 2; mt++)                                           \
            _Pragma("unroll")                                                    \
            for (int nt = 0; nt < 6; nt++)                                       \
                mma_tf32(ACC[mt][nt], a[mt], bb[nt]);                            \
    }                                                                            \
} while (0)

#define C3_LOADW(Wsrc, ko) do {                                                  \
    _Pragma("unroll")                                                            \
    for (int r = 0; r < 3; r++) {                                                \
        int f = tid + 512 * r;                                                   \
        pw[r] = *(const float4*)((Wsrc) + (size_t)(f >> 3) * C_ + (ko) + (f & 7) * 4); \
    }                                                                            \
} while (0)

#define C3_STOREW(dWpt) do {                                                     \
    _Pragma("unroll")                                                            \
    for (int r = 0; r < 3; r++) {                                                \
        int f = tid + 512 * r;                                                   \
        *(float4*)&(dWpt)[(f >> 3) * SAS + (f & 7) * 4] = to_tf32_4(pw[r]);      \
    }                                                                            \
} while (0)

#define C3_ZEROACC(ACC) do {                                                     \
    _Pragma("unroll")                                                            \
    for (int mt = 0; mt < 2; mt++)                                               \
        _Pragma("unroll")                                                        \
        for (int nt = 0; nt < 6; nt++)                                           \
            _Pragma("unroll")                                                    \
            for (int r = 0; r < 4; r++) ACC[mt][nt][r] = 0.f;                    \
} while (0)

// epilogue to smem sO (tf32-rounded), optional gelu
#define C3_EPI_SMEM(ACC, biasp, do_gelu) do {                                    \
    float bv0, bv1;                                                              \
    _Pragma("unroll")                                                            \
    for (int nt = 0; nt < 6; nt++) {                                             \
        int o = nbase + nt * 8 + 2 * tig;                                        \
        bv0 = __ldg(&(biasp)[o]); bv1 = __ldg(&(biasp)[o + 1]);                  \
        _Pragma("unroll")                                                        \
        for (int mt = 0; mt < 2; mt++)                                           \
            _Pragma("unroll")                                                    \
            for (int half = 0; half < 2; half++) {                               \
                int row = mbase + mt * 16 + g + half * 8;                        \
                float v0 = ACC[mt][nt][half * 2 + 0] + bv0;                      \
                float v1 = ACC[mt][nt][half * 2 + 1] + bv1;                      \
                if (do_gelu) {                                                   \
                    v0 = 0.5f * v0 * (1.0f + erff(v0 * 0.70710678118654752f));   \
                    v1 = 0.5f * v1 * (1.0f + erff(v1 * 0.70710678118654752f));   \
                }                                                                \
                float2 w = {to_tf32(v0), to_tf32(v1)};                           \
                *(float2*)&sO[row * C3_SO_STRIDE + o] = w;                       \
            }                                                                    \
    }                                                                            \
} while (0)

__global__ __launch_bounds__(512, 1) void conv3x_kernel(
    const float* __restrict__ Acl,
    const float* __restrict__ Wp,  const float* __restrict__ bp,
    const float* __restrict__ Wm1, const float* __restrict__ bm1,
    const float* __restrict__ Wm2, const float* __restrict__ bm2,
    const float* __restrict__ r1,  const float* __restrict__ r2,
    float* __restrict__ out)
{
    extern __shared__ float sm[];
    float* sO = sm;                      // 128 x 196 intermediate (aliases dA bufs)
    float* sW = sm + C3_W_OFF;           // 2 W buffers
    const int tid = threadIdx.x;
    const int lane = tid & 31;
    const int g = lane >> 2;
    const int tig = lane & 3;
    const int wid = tid >> 5;
    const int mbase = (wid & 3) * 32;
    const int nbase = (wid >> 2) * 48;
    const int t = blockIdx.x;
    const float* Arow = Acl + (size_t)t * TILE_ELEMS;

    float acc[2][6][4];
    float4 pa[2], pw[3];

    // ---------- GEMM1: D1 = fus @ Wp^T + bp ----------
    C3_ZEROACC(acc);
#pragma unroll
    for (int r = 0; r < 2; r++) {
        int f = tid + 512 * r;
        pa[r] = *(const float4*)(Arow + (size_t)(f >> 3) * C_ + (f & 7) * 4);
    }
    C3_LOADW(Wp, 0);
    for (int kc = 0; kc < 6; kc++) {
        float* dA = sm + (kc & 1) * CONV_ABUF;
        float* dW = sW + (kc & 1) * CONV_WBUF;
#pragma unroll
        for (int r = 0; r < 2; r++) {
            int f = tid + 512 * r;
            *(float4*)&dA[(f >> 3) * SAS + (f & 7) * 4] = pa[r];
        }
        C3_STOREW(dW);
        __syncthreads();
        if (kc < 5) {
            int ko = (kc + 1) * 32;
#pragma unroll
            for (int r = 0; r < 2; r++) {
                int f = tid + 512 * r;
                pa[r] = *(const float4*)(Arow + (size_t)(f >> 3) * C_ + ko + (f & 7) * 4);
            }
            C3_LOADW(Wp, ko);
        }
        C3_MMALOOP(dA, SAS, 0, dW, acc);
    }
    __syncthreads();
    C3_EPI_SMEM(acc, bp, 0);
    __syncthreads();

    // ---------- GEMM2: D2 = gelu(D1 @ Wm1^T + bm1) ----------
    C3_ZEROACC(acc);
    C3_LOADW(Wm1, 0);
    for (int kc = 0; kc < 6; kc++) {
        float* dW = sW + (kc & 1) * CONV_WBUF;
        C3_STOREW(dW);
        __syncthreads();
        if (kc < 5) C3_LOADW(Wm1, (kc + 1) * 32);
        C3_MMALOOP(sO, C3_SO_STRIDE, kc * 32, dW, acc);
    }
    __syncthreads();
    C3_EPI_SMEM(acc, bm1, 1);
    __syncthreads();

    // ---------- GEMM3: out = D2 @ Wm2^T + bm2 + x1 + x2 (channel-first) ----------
    C3_ZEROACC(acc);
    C3_LOADW(Wm2, 0);
    for (int kc = 0; kc < 6; kc++) {
        float* dW = sW + (kc & 1) * CONV_WBUF;
        C3_STOREW(dW);
        __syncthreads();
        if (kc < 5) C3_LOADW(Wm2, (kc + 1) * 32);
        C3_MMALOOP(sO, C3_SO_STRIDE, kc * 32, dW, acc);
    }

    const int pg0 = t << 7;
    const int b = pg0 >> 14;
    const int p0 = pg0 & (HW_ - 1);
#pragma unroll
    for (int nt = 0; nt < 6; nt++) {
        int o = nbase + nt * 8 + 2 * tig;
        float bv0 = __ldg(&bm2[o]);
        float bv1 = __ldg(&bm2[o + 1]);
#pragma unroll
        for (int mt = 0; mt < 2; mt++)
#pragma unroll
            for (int half = 0; half < 2; half++) {
                int row = mbase + mt * 16 + g + half * 8;
#pragma unroll
                for (int cc = 0; cc < 2; cc++) {
                    float v = acc[mt][nt][half * 2 + cc] + (cc ? bv1 : bv0);
                    size_t idx = ((size_t)(b * C_ + o + cc) << 14) + p0 + row;
                    v += __ldg(&r1[idx]) + __ldg(&r2[idx]);
                    out[idx] = v;
                }
            }
    }
}

// ---------------- shared constants for attn/av (256 thr, M-split 64) ----------------
#define PAS 68
#define AB_A (64 * PAS)
#define AB_B (128 * PAS)
#define PBUF (AB_A + AB_B)
#define PIPE_SMEM_BYTES (2 * PBUF * 4)

#define PIPE_STAGE(sbuf32, Ap, Bp) do {                                          \
    _Pragma("unroll")                                                            \
    for (int r = 0; r < 4; r++) {                                                \
        int f = tid + 256 * r;                                                   \
        int row = f >> 4, c4 = f & 15;                                           \
        cpa16((sbuf32) + (row * PAS + c4 * 4) * 4, (Ap) + row * 128 + c4 * 4);   \
    }                                                                            \
    _Pragma("unroll")                                                            \
    for (int r = 0; r < 8; r++) {                                                \
        int f = tid + 256 * r;                                                   \
        int row = f >> 4, c4 = f & 15;                                           \
        cpa16((sbuf32) + (AB_A + row * PAS + c4 * 4) * 4, (Bp) + row * 128 + c4 * 4); \
    }                                                                            \
    CP_COMMIT();                                                                 \
} while (0)

#define PIPE_MMA(dA, dB, ACC) do {                                               \
    _Pragma("unroll")                                                            \
    for (int k4 = 0; k4 < 8; k4++) {                                             \
        const int k0 = k4 * 8 + tig;                                             \
        uint32_t a[2][4], bf[4][2];                                              \
        _Pragma("unroll")                                                        \
        for (int mt = 0; mt < 2; mt++) {                                         \
            int row = mbase + mt * 16 + g;                                       \
            a[mt][0] = __float_as_uint((dA)[row * PAS + k0]);                    \
            a[mt][1] = __float_as_uint((dA)[(row + 8) * PAS + k0]);              \
            a[mt][2] = __float_as_uint((dA)[row * PAS + k0 + 4]);                \
            a[mt][3] = __float_as_uint((dA)[(row + 8) * PAS + k0 + 4]);          \
        }                                                                        \
        _Pragma("unroll")                                                        \
        for (int nt = 0; nt < 4; nt++) {                                         \
            int col = nbase + nt * 8 + g;                                        \
            bf[nt][0] = __float_as_uint((dB)[col * PAS + k0]);                   \
            bf[nt][1] = __float_as_uint((dB)[col * PAS + k0 + 4]);               \
        }                                                                        \
        _Pragma("unroll")                                                        \
        for (int mt = 0; mt < 2; mt++)                                           \
            _Pragma("unroll")                                                    \
            for (int nt = 0; nt < 4; nt++)                                       \
                mma_tf32(ACC[mt][nt], a[mt], bf[nt]);                            \
    }                                                                            \
} while (0)

// ---------------- attention: 256 thr, M-split, cp.async pipeline ----------------
__global__ __launch_bounds__(256, 2) void attn_mma_kernel(
    const float* __restrict__ o1, const float* __restrict__ o2,
    const float* __restrict__ o1t, const float* __restrict__ o2t,
    const float* __restrict__ n1h, const float* __restrict__ n2h,
    const float* __restrict__ n1w, const float* __restrict__ n2w,
    const float* __restrict__ pbh, const float* __restrict__ pbw,
    float* __restrict__ attn1, float* __restrict__ attn2)
{
    extern __shared__ float sm[];
    const uint32_t sbase = (uint32_t)__cvta_generic_to_shared(sm);
    const int bh = blockIdx.x;
    const int mode = blockIdx.y;
    const int mh = blockIdx.z;
    const int hd = bh & 7, b = bh >> 3;
    const int tid = threadIdx.x;
    const int lane = tid & 31, g = lane >> 2, tig = lane & 3;
    const int wid = tid >> 5;
    const int mbase = (wid & 1) * 32;
    const int nbase = (wid >> 1) * 32;
    const int mh64 = mh * 64;
    const float* Abase = ((mode ? o1t : o2) + ((size_t)b * C_ + hd * CPH_) * HW_) + mh64 * 128;
    const float* Bbase = (mode ? o2t : o1) + ((size_t)b * C_ + hd * CPH_) * HW_;

    float acc[2][4][4];
#pragma unroll
    for (int mt = 0; mt < 2; mt++)
#pragma unroll
        for (int nt = 0; nt < 4; nt++)
#pragma unroll
            for (int e = 0; e < 4; e++) acc[mt][nt][e] = 0.f;

    PIPE_STAGE(sbase, Abase, Bbase);
    for (int kc = 0; kc < 48; kc++) {
        if (kc < 47) {
            int kn = kc + 1;
            const float* Ap = Abase + (kn >> 1) * HW_ + (kn & 1) * 64;
            const float* Bp = Bbase + (kn >> 1) * HW_ + (kn & 1) * 64;
            uint32_t sbuf = sbase + ((kn & 1) * PBUF) * 4;
            PIPE_STAGE(sbuf, Ap, Bp);
            CP_WAIT1();
        } else {
            CP_WAIT0();
        }
        __syncthreads();
        const float* dA = sm + (kc & 1) * PBUF;
        const float* dB = dA + AB_A;
        PIPE_MMA(dA, dB, acc);
        __syncthreads();
    }

    const float* nI = mode ? n1w : n2h;
    const float* nJ = mode ? n2w : n1h;
    const float bias = mode ? __ldg(&pbw[hd]) : __ldg(&pbh[hd]);
    float rinv[4], cinv[8];
#pragma unroll
    for (int mt = 0; mt < 2; mt++)
#pragma unroll
        for (int half = 0; half < 2; half++) {
            int row = mbase + mt * 16 + g + half * 8;
            rinv[mt * 2 + half] = TEMP_INV / fmaxf(__ldg(&nI[bh * 128 + mh64 + row]), EPS_);
        }
#pragma unroll
    for (int nt = 0; nt < 4; nt++)
#pragma unroll
        for (int cc = 0; cc < 2; cc++) {
            int col = nbase + nt * 8 + 2 * tig + cc;
            cinv[nt * 2 + cc] = 1.f / fmaxf(__ldg(&nJ[bh * 128 + col]), EPS_);
        }
    float* sc = sm;
#pragma unroll
    for (int mt = 0; mt < 2; mt++)
#pragma unroll
        for (int half = 0; half < 2; half++) {
            int row = mbase + mt * 16 + g + half * 8;
            float ri = rinv[mt * 2 + half];
#pragma unroll
            for (int nt = 0; nt < 4; nt++) {
                int col = nbase + nt * 8 + 2 * tig;
                float2 v;
                v.x = acc[mt][nt][half * 2 + 0] * (ri * cinv[nt * 2 + 0]) + bias;
                v.y = acc[mt][nt][half * 2 + 1] * (ri * cinv[nt * 2 + 1]) + bias;
                *(float2*)&sc[row * 132 + col] = v;
            }
        }
    __syncthreads();

    float* outp = (mode ? attn2 : attn1) + (size_t)bh * HW_ + mh64 * 128;
    for (int r = wid; r < 64; r += 8) {
        float4 v = *(float4*)&sc[r * 132 + lane * 4];
        float m = fmaxf(fmaxf(v.x, v.y), fmaxf(v.z, v.w));
#pragma unroll
        for (int s = 16; s >= 1; s >>= 1) m = fmaxf(m, __shfl_xor_sync(0xffffffffu, m, s));
        v.x = __expf(v.x - m); v.y = __expf(v.y - m);
        v.z = __expf(v.z - m); v.w = __expf(v.w - m);
        float su = v.x + v.y + v.z + v.w;
#pragma unroll
        for (int s = 16; s >= 1; s >>= 1) su += __shfl_xor_sync(0xffffffffu, su, s);
        float inv = 1.f / su;
        v.x *= inv; v.y *= inv; v.z *= inv; v.w *= inv;
        *(float4*)&outp[r * 128 + lane * 4] = to_tf32_4(v);
    }
}

// ---------------- AV + q-residual + gated fusion: 256 thr, M-split, cp.async ----------------
__global__ __launch_bounds__(256, 2) void av_mma_kernel(
    const float* __restrict__ o1, const float* __restrict__ o2,
    const float* __restrict__ o1t,
    const float* __restrict__ attn1, const float* __restrict__ attn2,
    const float* __restrict__ n2h, const float* __restrict__ n1w,
    const float* __restrict__ gate, float* __restrict__ fus)
{
    extern __shared__ float sm[];
    const uint32_t sbase = (uint32_t)__cvta_generic_to_shared(sm);
    const int ch = blockIdx.x, b = blockIdx.y;
    const int mh = blockIdx.z;
    const int hd = ch / CPH_;
    const int bh = b * 8 + hd;
    const int tid = threadIdx.x;
    const int lane = tid & 31, g = lane >> 2, tig = lane & 3;
    const int wid = tid >> 5;
    const int mbase = (wid & 1) * 32;
    const int nbase = (wid >> 1) * 32;
    const int mh64 = mh * 64;

    const float* A1 = attn1 + (size_t)bh * HW_ + mh64 * 128;
    const float* B1 = o1t + ((size_t)b * C_ + ch) * HW_;
    const float* A2 = o2 + ((size_t)b * C_ + ch) * HW_ + mh64 * 128;
    const float* B2 = attn2 + (size_t)bh * HW_;
    const float* S1 = o1 + ((size_t)b * C_ + ch) * HW_;
    const float* S2 = o2 + ((size_t)b * C_ + ch) * HW_;

    float acc1[2][4][4], acc2[2][4][4];
#pragma unroll
    for (int mt = 0; mt < 2; mt++)
#pragma unroll
        for (int nt = 0; nt < 4; nt++)
#pragma unroll
            for (int e = 0; e < 4; e++) { acc1[mt][nt][e] = 0.f; acc2[mt][nt][e] = 0.f; }

    const uint32_t sb0 = sbase;
    const uint32_t sb1 = sbase + PBUF * 4;
    const float* dA0 = sm;
    const float* dB0 = sm + AB_A;
    const float* dA1 = sm + PBUF;
    const float* dB1 = sm + PBUF + AB_A;

    PIPE_STAGE(sb0, A1, B1);
    PIPE_STAGE(sb1, A1 + 64, B1 + 64);
    CP_WAIT1(); __syncthreads();
    PIPE_MMA(dA0, dB0, acc1);
    __syncthreads();
    PIPE_STAGE(sb0, A2, B2);
    CP_WAIT1(); __syncthreads();
    PIPE_MMA(dA1, dB1, acc1);
    __syncthreads();
    PIPE_STAGE(sb1, A2 + 64, B2 + 64);
    CP_WAIT1(); __syncthreads();
    PIPE_MMA(dA0, dB0, acc2);
    CP_WAIT0(); __syncthreads();
    PIPE_MMA(dA1, dB1, acc2);

    const float gg = 1.f / (1.f + expf(-__ldg(&gate[0])));
    float invy[4], invx[8];
#pragma unroll
    for (int mt = 0; mt < 2; mt++)
#pragma unroll
        for (int half = 0; half < 2; half++) {
            int row = mbase + mt * 16 + g + half * 8;
            invy[mt * 2 + half] = 1.f / fmaxf(__ldg(&n2h[bh * 128 + mh64 + row]), EPS_);
        }
#pragma unroll
    for (int nt = 0; nt < 4; nt++)
#pragma unroll
        for (int cc = 0; cc < 2; cc++) {
            int col = nbase + nt * 8 + 2 * tig + cc;
            invx[nt * 2 + cc] = 1.f / fmaxf(__ldg(&n1w[bh * 128 + col]), EPS_);
        }

    float* fout = fus + ((size_t)b * C_ + ch) * HW_;
#pragma unroll
    for (int mt = 0; mt < 2; mt++)
#pragma unroll
        for (int half = 0; half < 2; half++) {
            int rl = mbase + mt * 16 + g + half * 8;
            int row = mh64 + rl;
            float iy = invy[mt * 2 + half];
#pragma unroll
            for (int nt = 0; nt < 4; nt++) {
                int col = nbase + nt * 8 + 2 * tig;
                float2 s1v = *(const float2*)(S1 + row * 128 + col);
                float2 s2v = *(const float2*)(S2 + row * 128 + col);
                float2 o;
                o.x = gg * (acc1[mt][nt][half * 2 + 0] + s2v.x * iy)
                    + (1.f - gg) * (acc2[mt][nt][half * 2 + 0] + s1v.x * invx[nt * 2 + 0]);
                o.y = gg * (acc1[mt][nt][half * 2 + 1] + s2v.y * iy)
                    + (1.f - gg) * (acc2[mt][nt][half * 2 + 1] + s1v.y * invx[nt * 2 + 1]);
                *(float2*)(fout + row * 128 + col) = o;
            }
        }
}

// ---------------- host launcher ----------------
extern "C" void kernel_launch(void* const* d_in, const int* in_sizes, int n_in,
                              void* d_out, int out_size)
{
    const float* x1  = (const float*)d_in[0];
    const float* x2  = (const float*)d_in[1];
    const float* Wp  = (const float*)d_in[2];
    const float* bp  = (const float*)d_in[3];
    const float* gate= (const float*)d_in[4];
    const float* pbh = (const float*)d_in[5];
    const float* pbw = (const float*)d_in[6];
    const float* Wm1 = (const float*)d_in[7];
    const float* bm1 = (const float*)d_in[8];
    const float* Wm2 = (const float*)d_in[9];
    const float* bm2 = (const float*)d_in[10];
    float* out = (float*)d_out;

    float *p_o1, *p_o2, *p_o1t, *p_o2t, *p_fus, *p_cl, *p_a1, *p_a2;
    float *p_n1h, *p_n2h, *p_n1w, *p_n2w;
    cudaGetSymbolAddress((void**)&p_o1, g_o1);
    cudaGetSymbolAddress((void**)&p_o2, g_o2);
    cudaGetSymbolAddress((void**)&p_o1t, g_o1t);
    cudaGetSymbolAddress((void**)&p_o2t, g_o2t);
    cudaGetSymbolAddress((void**)&p_fus, g_fus);
    cudaGetSymbolAddress((void**)&p_cl, g_cl);
    cudaGetSymbolAddress((void**)&p_a1, g_attn1);
    cudaGetSymbolAddress((void**)&p_a2, g_attn2);
    cudaGetSymbolAddress((void**)&p_n1h, g_n1h);
    cudaGetSymbolAddress((void**)&p_n2h, g_n2h);
    cudaGetSymbolAddress((void**)&p_n1w, g_n1w);
    cudaGetSymbolAddress((void**)&p_n2w, g_n2w);

    cudaFuncSetAttribute(conv_mma_kernel, cudaFuncAttributeMaxDynamicSharedMemorySize, SMEM_BYTES);
    cudaFuncSetAttribute(conv3x_kernel, cudaFuncAttributeMaxDynamicSharedMemorySize, C3_SMEM_BYTES);
    cudaFuncSetAttribute(attn_mma_kernel, cudaFuncAttributeMaxDynamicSharedMemorySize, PIPE_SMEM_BYTES);
    cudaFuncSetAttribute(av_mma_kernel, cudaFuncAttributeMaxDynamicSharedMemorySize, PIPE_SMEM_BYTES);

    dim3 tGrid(HW_ / 32, C_ / 32, B_);
    dim3 tBlk(32, 8);
    dim3 rGrid(16, C_, B_);

    // out1 = conv(x1), out2 = conv(x2): channel-first, tf32-rounded
    transpose_cf_cl_kernel<<<tGrid, tBlk>>>(x1, p_cl);
    conv_mma_kernel<<<NTILES_, 512, SMEM_BYTES>>>(p_cl, Wp, bp, p_o1, 8, nullptr, nullptr);
    transpose_cf_cl_kernel<<<tGrid, tBlk>>>(x2, p_cl);
    conv_mma_kernel<<<NTILES_, 512, SMEM_BYTES>>>(p_cl, Wp, bp, p_o2, 8, nullptr, nullptr);

    // repack + fused norms
    norm_init_kernel<<<32, 256>>>(p_n1h, p_n1w, p_n2h, p_n2w);
    repack_norm_kernel<<<rGrid, tBlk>>>(p_o1, p_o1t, p_n1h, p_n1w);
    repack_norm_kernel<<<rGrid, tBlk>>>(p_o2, p_o2t, p_n2h, p_n2w);
    norm_fin_kernel<<<32, 256>>>(p_n1h, p_n1w, p_n2h, p_n2w);

    attn_mma_kernel<<<dim3(B_ * HEADS_, 2, 2), 256, PIPE_SMEM_BYTES>>>(
        p_o1, p_o2, p_o1t, p_o2t, p_n1h, p_n2h, p_n1w, p_n2w, pbh, pbw, p_a1, p_a2);

    av_mma_kernel<<<dim3(C_, B_, 2), 256, PIPE_SMEM_BYTES>>>(
        p_o1, p_o2, p_o1t, p_a1, p_a2, p_n2h, p_n1w, gate, p_fus);

    // fused tail: conv(Wp) -> gelu(conv(Wm1)) -> conv(Wm2) + x1 + x2
    transpose_cf_cl_kernel<<<tGrid, tBlk>>>(p_fus, p_cl);
    conv3x_kernel<<<NTILES_, 512, C3_SMEM_BYTES>>>(p_cl, Wp, bp, Wm1, bm1, Wm2, bm2,
                                                   x1, x2, out);

    (void)in_sizes; (void)n_in; (void)out_size;
}

// round 9
// speedup vs baseline: 2.0848x; 1.1921x over previous
#include <cuda_runtime.h>
#include <math.h>
#include <stdint.h>

#define B_ 8
#define C_ 192
#define H_ 128
#define W_ 128
#define HW_ 16384
#define HEADS_ 8
#define CPH_ 24
#define TEMP_INV 100.0f
#define EPS_ 1e-12f

#define NPIX_ (B_ * HW_)
#define NTILES_ (NPIX_ / 128)

// ---------------- scratch ----------------
__device__ float g_o1[(size_t)B_ * C_ * HW_];
__device__ float g_o2[(size_t)B_ * C_ * HW_];
__device__ float g_o1t[(size_t)B_ * C_ * HW_];
__device__ float g_o2t[(size_t)B_ * C_ * HW_];
__device__ float g_fus[(size_t)B_ * C_ * HW_];
__device__ float g_attn1[(size_t)B_ * HEADS_ * HW_];
__device__ float g_attn2[(size_t)B_ * HEADS_ * HW_];
__device__ float g_n1h[B_ * HEADS_ * H_];
__device__ float g_n2h[B_ * HEADS_ * H_];
__device__ float g_n1w[B_ * HEADS_ * W_];
__device__ float g_n2w[B_ * HEADS_ * W_];

__device__ __forceinline__ float to_tf32(float x) {
    uint32_t u; asm("cvt.rna.tf32.f32 %0, %1;" : "=r"(u) : "f"(x));
    return __uint_as_float(u);
}
__device__ __forceinline__ float4 to_tf32_4(float4 v) {
    v.x = to_tf32(v.x); v.y = to_tf32(v.y); v.z = to_tf32(v.z); v.w = to_tf32(v.w);
    return v;
}

__device__ __forceinline__ void mma_tf32(float* c, const uint32_t* a, const uint32_t* b) {
    asm volatile(
        "mma.sync.aligned.m16n8k8.row.col.f32.tf32.tf32.f32 "
        "{%0,%1,%2,%3}, {%4,%5,%6,%7}, {%8,%9}, {%0,%1,%2,%3};"
        : "+f"(c[0]), "+f"(c[1]), "+f"(c[2]), "+f"(c[3])
        : "r"(a[0]), "r"(a[1]), "r"(a[2]), "r"(a[3]), "r"(b[0]), "r"(b[1]));
}

__device__ __forceinline__ void cpa16(uint32_t s, const void* g) {
    asm volatile("cp.async.cg.shared.global [%0], [%1], 16;" :: "r"(s), "l"(g));
}
#define CP_COMMIT() asm volatile("cp.async.commit_group;" ::: "memory")
#define CP_WAIT1()  asm volatile("cp.async.wait_group 1;" ::: "memory")
#define CP_WAIT0()  asm volatile("cp.async.wait_group 0;" ::: "memory")

// ---------------- repack + fused squared-sum norms (both sources in one launch) ----
__global__ __launch_bounds__(256) void repack_norm_kernel(
    const float* __restrict__ o1, const float* __restrict__ o2,
    float* __restrict__ o1t, float* __restrict__ o2t,
    float* __restrict__ n1h, float* __restrict__ n1w,
    float* __restrict__ n2h, float* __restrict__ n2w)
{
    __shared__ float t[32][33];
    __shared__ float cpart[8][32];
    const int cy = blockIdx.y;
    const int src = cy >= C_;
    const int c = src ? cy - C_ : cy;
    const int b = blockIdx.z;
    const int bh = b * 8 + c / CPH_;
    const int x0 = (blockIdx.x & 3) * 32, y0 = (blockIdx.x >> 2) * 32;
    const int tx = threadIdx.x, ty = threadIdx.y;
    const float* ib = (src ? o2 : o1) + ((size_t)b * C_ + c) * HW_;
    float* ob = (src ? o2t : o1t) + ((size_t)b * C_ + c) * HW_;
    float* rowAcc = (src ? n2h : n1h);
    float* colAcc = (src ? n2w : n1w);

    float colLoc = 0.f;
#pragma unroll
    for (int ii = 0; ii < 4; ii++) {
        int i = ty + 8 * ii;
        float v = ib[(y0 + i) * 128 + x0 + tx];
        t[i][tx] = v;
        float sq = v * v;
        colLoc += sq;
        float rs = sq;
#pragma unroll
        for (int s = 16; s >= 1; s >>= 1) rs += __shfl_xor_sync(0xffffffffu, rs, s);
        if (tx == 0) atomicAdd(&rowAcc[bh * 128 + y0 + i], rs);
    }
    cpart[ty][tx] = colLoc;
    __syncthreads();
#pragma unroll
    for (int i = ty; i < 32; i += 8)
        ob[(x0 + i) * 128 + y0 + tx] = t[tx][i];
    if (ty == 0) {
        float s = cpart[0][tx] + cpart[1][tx] + cpart[2][tx] + cpart[3][tx]
                + cpart[4][tx] + cpart[5][tx] + cpart[6][tx] + cpart[7][tx];
        atomicAdd(&colAcc[bh * 128 + x0 + tx], s);
    }
}

__global__ void norm_init_kernel(float* a, float* b, float* c, float* d) {
    int i = blockIdx.x * 256 + threadIdx.x;
    if (i < B_ * HEADS_ * 128) { a[i] = 0.f; b[i] = 0.f; c[i] = 0.f; d[i] = 0.f; }
}
__global__ void norm_fin_kernel(float* a, float* b, float* c, float* d) {
    int i = blockIdx.x * 256 + threadIdx.x;
    if (i < B_ * HEADS_ * 128) {
        a[i] = sqrtf(a[i]); b[i] = sqrtf(b[i]); c[i] = sqrtf(c[i]); d[i] = sqrtf(d[i]);
    }
}

// ---------------- conv1x1 from CHANNEL-FIRST input via mma.sync tf32 ----------------
// A chunk staged transposed: dA[k (32)][pix (128)], stride 136 (=8 mod 32):
//   global float4 along pixels (coalesced), smem float4 stores (conflict-free),
//   frag loads dA[k0*136 + row] hit 32 distinct banks.
#define SAS 36
#define ATS 136
#define CONV_ATBUF (32 * ATS)              // 4352 floats
#define CONV_WBUF (192 * SAS)              // 6912 floats
#define SMEM_BYTES ((2 * CONV_ATBUF + 2 * CONV_WBUF) * 4)   // 90112

// grid (NTILES, 2): y selects (x1->o1) or (x2->o2)
__global__ __launch_bounds__(512, 1) void conv_front_kernel(
    const float* __restrict__ x1, const float* __restrict__ x2,
    const float* __restrict__ Wt, const float* __restrict__ bias,
    float* __restrict__ o1, float* __restrict__ o2)
{
    extern __shared__ float sm[];
    const int tid = threadIdx.x;
    const int lane = tid & 31;
    const int g = lane >> 2;
    const int tig = lane & 3;
    const int wid = tid >> 5;
    const int mbase = (wid & 3) * 32;
    const int nbase = (wid >> 2) * 48;
    const int t = blockIdx.x;
    const int pg0 = t << 7;
    const int b = pg0 >> 14;
    const int p0 = pg0 & (HW_ - 1);
    const float* inb = (blockIdx.y ? x2 : x1) + (size_t)b * C_ * HW_;
    float* out = (blockIdx.y ? o2 : o1);

    float c[2][6][4];
#pragma unroll
    for (int mt = 0; mt < 2; mt++)
#pragma unroll
        for (int nt = 0; nt < 6; nt++)
#pragma unroll
            for (int r = 0; r < 4; r++) c[mt][nt][r] = 0.f;

    float4 pa[2], pw[3];
#pragma unroll
    for (int r = 0; r < 2; r++) {
        int f = tid + 512 * r;              // 0..1023: k = f>>5 (32), p4 = f&31
        pa[r] = *(const float4*)(inb + (size_t)(f >> 5) * HW_ + p0 + (f & 31) * 4);
    }
#pragma unroll
    for (int r = 0; r < 3; r++) {
        int f = tid + 512 * r;
        pw[r] = *(const float4*)(Wt + (size_t)(f >> 3) * C_ + (f & 7) * 4);
    }

    for (int kc = 0; kc < 6; kc++) {
        float* dA = sm + (kc & 1) * CONV_ATBUF;
        float* dW = sm + 2 * CONV_ATBUF + (kc & 1) * CONV_WBUF;
#pragma unroll
        for (int r = 0; r < 2; r++) {
            int f = tid + 512 * r;
            *(float4*)&dA[(f >> 5) * ATS + (f & 31) * 4] = to_tf32_4(pa[r]);
        }
#pragma unroll
        for (int r = 0; r < 3; r++) {
            int f = tid + 512 * r;
            *(float4*)&dW[(f >> 3) * SAS + (f & 7) * 4] = to_tf32_4(pw[r]);
        }
        __syncthreads();
        if (kc < 5) {
            int ko = (kc + 1) * 32;
#pragma unroll
            for (int r = 0; r < 2; r++) {
                int f = tid + 512 * r;
                pa[r] = *(const float4*)(inb + (size_t)(ko + (f >> 5)) * HW_ + p0 + (f & 31) * 4);
            }
#pragma unroll
            for (int r = 0; r < 3; r++) {
                int f = tid + 512 * r;
                pw[r] = *(const float4*)(Wt + (size_t)(f >> 3) * C_ + ko + (f & 7) * 4);
            }
        }
#pragma unroll
        for (int kk = 0; kk < 4; kk++) {
            const int k0 = kk * 8 + tig;
            uint32_t a[2][4], bb[6][2];
#pragma unroll
            for (int mt = 0; mt < 2; mt++) {
                int row = mbase + mt * 16 + g;
                a[mt][0] = __float_as_uint(dA[k0 * ATS + row]);
                a[mt][1] = __float_as_uint(dA[k0 * ATS + row + 8]);
                a[mt][2] = __float_as_uint(dA[(k0 + 4) * ATS + row]);
                a[mt][3] = __float_as_uint(dA[(k0 + 4) * ATS + row + 8]);
            }
#pragma unroll
            for (int nt = 0; nt < 6; nt++) {
                int col = nbase + nt * 8 + g;
                bb[nt][0] = __float_as_uint(dW[col * SAS + k0]);
                bb[nt][1] = __float_as_uint(dW[col * SAS + k0 + 4]);
            }
#pragma unroll
            for (int mt = 0; mt < 2; mt++)
#pragma unroll
                for (int nt = 0; nt < 6; nt++)
                    mma_tf32(c[mt][nt], a[mt], bb[nt]);
        }
    }

    // epilogue: channel-first, tf32-rounded
#pragma unroll
    for (int nt = 0; nt < 6; nt++) {
        int o = nbase + nt * 8 + 2 * tig;
        float bv0 = __ldg(&bias[o]);
        float bv1 = __ldg(&bias[o + 1]);
#pragma unroll
        for (int mt = 0; mt < 2; mt++)
#pragma unroll
            for (int half = 0; half < 2; half++) {
                int row = mbase + mt * 16 + g + half * 8;
#pragma unroll
                for (int cc = 0; cc < 2; cc++) {
                    float v = c[mt][nt][half * 2 + cc] + (cc ? bv1 : bv0);
                    out[((size_t)(b * C_ + o + cc) << 14) + p0 + row] = to_tf32(v);
                }
            }
    }
}

// ---------------- fused triple conv (channel-first fus input) ----------------
// GEMM1 A staged like conv_front (transposed, tf32-rounded); intermediates in sO.
#define C3_SO_STRIDE 196
#define C3_SO_FLOATS (128 * C3_SO_STRIDE)      // 25088 (> 2*CONV_ATBUF = 8704, aliased)
#define C3_W_OFF C3_SO_FLOATS
#define C3_SMEM_BYTES ((C3_SO_FLOATS + 2 * CONV_WBUF) * 4)  // 155648

#define C3_MMALOOP_SO(kbase, dWpt, ACC) do {                                     \
    _Pragma("unroll")                                                            \
    for (int kk = 0; kk < 4; kk++) {                                             \
        const int k0 = kk * 8 + tig;                                             \
        uint32_t a[2][4], bb[6][2];                                              \
        _Pragma("unroll")                                                        \
        for (int mt = 0; mt < 2; mt++) {                                         \
            int row = mbase + mt * 16 + g;                                       \
            a[mt][0] = __float_as_uint(sO[row * C3_SO_STRIDE + (kbase) + k0]);   \
            a[mt][1] = __float_as_uint(sO[(row + 8) * C3_SO_STRIDE + (kbase) + k0]); \
            a[mt][2] = __float_as_uint(sO[row * C3_SO_STRIDE + (kbase) + k0 + 4]); \
            a[mt][3] = __float_as_uint(sO[(row + 8) * C3_SO_STRIDE + (kbase) + k0 + 4]); \
        }                                                                        \
        _Pragma("unroll")                                                        \
        for (int nt = 0; nt < 6; nt++) {                                         \
            int col = nbase + nt * 8 + g;                                        \
            bb[nt][0] = __float_as_uint((dWpt)[col * SAS + k0]);                 \
            bb[nt][1] = __float_as_uint((dWpt)[col * SAS + k0 + 4]);             \
        }                                                                        \
        _Pragma("unroll")                                                        \
        for (int mt = 0; mt < 2; mt++)                                           \
            _Pragma("unroll")                                                    \
            for (int nt = 0; nt < 6; nt++)                                       \
                mma_tf32(ACC[mt][nt], a[mt], bb[nt]);                            \
    }                                                                            \
} while (0)

#define C3_LOADW(Wsrc, ko) do {                                                  \
    _Pragma("unroll")                                                            \
    for (int r = 0; r < 3; r++) {                                                \
        int f = tid + 512 * r;                                                   \
        pw[r] = *(const float4*)((Wsrc) + (size_t)(f >> 3) * C_ + (ko) + (f & 7) * 4); \
    }                                                                            \
} while (0)

#define C3_STOREW(dWpt) do {                                                     \
    _Pragma("unroll")                                                            \
    for (int r = 0; r < 3; r++) {                                                \
        int f = tid + 512 * r;                                                   \
        *(float4*)&(dWpt)[(f >> 3) * SAS + (f & 7) * 4] = to_tf32_4(pw[r]);      \
    }                                                                            \
} while (0)

#define C3_ZEROACC(ACC) do {                                                     \
    _Pragma("unroll")                                                            \
    for (int mt = 0; mt < 2; mt++)                                               \
        _Pragma("unroll")                                                        \
        for (int nt = 0; nt < 6; nt++)                                           \
            _Pragma("unroll")                                                    \
            for (int r = 0; r < 4; r++) ACC[mt][nt][r] = 0.f;                    \
} while (0)

#define C3_EPI_SMEM(ACC, biasp, do_gelu) do {                                    \
    _Pragma("unroll")                                                            \
    for (int nt = 0; nt < 6; nt++) {                                             \
        int o = nbase + nt * 8 + 2 * tig;                                        \
        float bv0 = __ldg(&(biasp)[o]);                                          \
        float bv1 = __ldg(&(biasp)[o + 1]);                                      \
        _Pragma("unroll")                                                        \
        for (int mt = 0; mt < 2; mt++)                                           \
            _Pragma("unroll")                                                    \
            for (int half = 0; half < 2; half++) {                               \
                int row = mbase + mt * 16 + g + half * 8;                        \
                float v0 = ACC[mt][nt][half * 2 + 0] + bv0;                      \
                float v1 = ACC[mt][nt][half * 2 + 1] + bv1;                      \
                if (do_gelu) {                                                   \
                    v0 = 0.5f * v0 * (1.0f + erff(v0 * 0.70710678118654752f));   \
                    v1 = 0.5f * v1 * (1.0f + erff(v1 * 0.70710678118654752f));   \
                }                                                                \
                float2 w = {to_tf32(v0), to_tf32(v1)};                           \
                *(float2*)&sO[row * C3_SO_STRIDE + o] = w;                       \
            }                                                                    \
    }                                                                            \
} while (0)

__global__ __launch_bounds__(512, 1) void conv3x_kernel(
    const float* __restrict__ fus,
    const float* __restrict__ Wp,  const float* __restrict__ bp,
    const float* __restrict__ Wm1, const float* __restrict__ bm1,
    const float* __restrict__ Wm2, const float* __restrict__ bm2,
    const float* __restrict__ r1,  const float* __restrict__ r2,
    float* __restrict__ out)
{
    extern __shared__ float sm[];
    float* sO = sm;
    float* sW = sm + C3_W_OFF;
    const int tid = threadIdx.x;
    const int lane = tid & 31;
    const int g = lane >> 2;
    const int tig = lane & 3;
    const int wid = tid >> 5;
    const int mbase = (wid & 3) * 32;
    const int nbase = (wid >> 2) * 48;
    const int t = blockIdx.x;
    const int pg0 = t << 7;
    const int b = pg0 >> 14;
    const int p0 = pg0 & (HW_ - 1);
    const float* inb = fus + (size_t)b * C_ * HW_;

    float acc[2][6][4];
    float4 pa[2], pw[3];

    // ---------- GEMM1: D1 = fus @ Wp^T + bp (A staged transposed from channel-first)
    C3_ZEROACC(acc);
#pragma unroll
    for (int r = 0; r < 2; r++) {
        int f = tid + 512 * r;
        pa[r] = *(const float4*)(inb + (size_t)(f >> 5) * HW_ + p0 + (f & 31) * 4);
    }
    C3_LOADW(Wp, 0);
    for (int kc = 0; kc < 6; kc++) {
        float* dA = sm + (kc & 1) * CONV_ATBUF;   // aliases low part of sO region
        float* dW = sW + (kc & 1) * CONV_WBUF;
#pragma unroll
        for (int r = 0; r < 2; r++) {
            int f = tid + 512 * r;
            *(float4*)&dA[(f >> 5) * ATS + (f & 31) * 4] = to_tf32_4(pa[r]);
        }
        C3_STOREW(dW);
        __syncthreads();
        if (kc < 5) {
            int ko = (kc + 1) * 32;
#pragma unroll
            for (int r = 0; r < 2; r++) {
                int f = tid + 512 * r;
                pa[r] = *(const float4*)(inb + (size_t)(ko + (f >> 5)) * HW_ + p0 + (f & 31) * 4);
            }
            C3_LOADW(Wp, ko);
        }
#pragma unroll
        for (int kk = 0; kk < 4; kk++) {
            const int k0 = kk * 8 + tig;
            uint32_t a[2][4], bb[6][2];
#pragma unroll
            for (int mt = 0; mt < 2; mt++) {
                int row = mbase + mt * 16 + g;
                a[mt][0] = __float_as_uint(dA[k0 * ATS + row]);
                a[mt][1] = __float_as_uint(dA[k0 * ATS + row + 8]);
                a[mt][2] = __float_as_uint(dA[(k0 + 4) * ATS + row]);
                a[mt][3] = __float_as_uint(dA[(k0 + 4) * ATS + row + 8]);
            }
#pragma unroll
            for (int nt = 0; nt < 6; nt++) {
                int col = nbase + nt * 8 + g;
                bb[nt][0] = __float_as_uint(dW[col * SAS + k0]);
                bb[nt][1] = __float_as_uint(dW[col * SAS + k0 + 4]);
            }
#pragma unroll
            for (int mt = 0; mt < 2; mt++)
#pragma unroll
                for (int nt = 0; nt < 6; nt++)
                    mma_tf32(acc[mt][nt], a[mt], bb[nt]);
        }
    }
    __syncthreads();
    C3_EPI_SMEM(acc, bp, 0);
    __syncthreads();

    // ---------- GEMM2: D2 = gelu(D1 @ Wm1^T + bm1) ----------
    C3_ZEROACC(acc);
    C3_LOADW(Wm1, 0);
    for (int kc = 0; kc < 6; kc++) {
        float* dW = sW + (kc & 1) * CONV_WBUF;
        C3_STOREW(dW);
        __syncthreads();
        if (kc < 5) C3_LOADW(Wm1, (kc + 1) * 32);
        C3_MMALOOP_SO(kc * 32, dW, acc);
    }
    __syncthreads();
    C3_EPI_SMEM(acc, bm1, 1);
    __syncthreads();

    // ---------- GEMM3: out = D2 @ Wm2^T + bm2 + x1 + x2 ----------
    C3_ZEROACC(acc);
    C3_LOADW(Wm2, 0);
    for (int kc = 0; kc < 6; kc++) {
        float* dW = sW + (kc & 1) * CONV_WBUF;
        C3_STOREW(dW);
        __syncthreads();
        if (kc < 5) C3_LOADW(Wm2, (kc + 1) * 32);
        C3_MMALOOP_SO(kc * 32, dW, acc);
    }

#pragma unroll
    for (int nt = 0; nt < 6; nt++) {
        int o = nbase + nt * 8 + 2 * tig;
        float bv0 = __ldg(&bm2[o]);
        float bv1 = __ldg(&bm2[o + 1]);
#pragma unroll
        for (int mt = 0; mt < 2; mt++)
#pragma unroll
            for (int half = 0; half < 2; half++) {
                int row = mbase + mt * 16 + g + half * 8;
#pragma unroll
                for (int cc = 0; cc < 2; cc++) {
                    float v = acc[mt][nt][half * 2 + cc] + (cc ? bv1 : bv0);
                    size_t idx = ((size_t)(b * C_ + o + cc) << 14) + p0 + row;
                    v += __ldg(&r1[idx]) + __ldg(&r2[idx]);
                    out[idx] = v;
                }
            }
    }
}

// ---------------- shared constants for attn/av (256 thr, M-split 64) ----------------
#define PAS 68
#define AB_A (64 * PAS)
#define AB_B (128 * PAS)
#define PBUF (AB_A + AB_B)
#define PIPE_SMEM_BYTES (2 * PBUF * 4)

#define PIPE_STAGE(sbuf32, Ap, Bp) do {                                          \
    _Pragma("unroll")                                                            \
    for (int r = 0; r < 4; r++) {                                                \
        int f = tid + 256 * r;                                                   \
        int row = f >> 4, c4 = f & 15;                                           \
        cpa16((sbuf32) + (row * PAS + c4 * 4) * 4, (Ap) + row * 128 + c4 * 4);   \
    }                                                                            \
    _Pragma("unroll")                                                            \
    for (int r = 0; r < 8; r++) {                                                \
        int f = tid + 256 * r;                                                   \
        int row = f >> 4, c4 = f & 15;                                           \
        cpa16((sbuf32) + (AB_A + row * PAS + c4 * 4) * 4, (Bp) + row * 128 + c4 * 4); \
    }                                                                            \
    CP_COMMIT();                                                                 \
} while (0)

#define PIPE_MMA(dA, dB, ACC) do {                                               \
    _Pragma("unroll")                                                            \
    for (int k4 = 0; k4 < 8; k4++) {                                             \
        const int k0 = k4 * 8 + tig;                                             \
        uint32_t a[2][4], bf[4][2];                                              \
        _Pragma("unroll")                                                        \
        for (int mt = 0; mt < 2; mt++) {                                         \
            int row = mbase + mt * 16 + g;                                       \
            a[mt][0] = __float_as_uint((dA)[row * PAS + k0]);                    \
            a[mt][1] = __float_as_uint((dA)[(row + 8) * PAS + k0]);              \
            a[mt][2] = __float_as_uint((dA)[row * PAS + k0 + 4]);                \
            a[mt][3] = __float_as_uint((dA)[(row + 8) * PAS + k0 + 4]);          \
        }                                                                        \
        _Pragma("unroll")                                                        \
        for (int nt = 0; nt < 4; nt++) {                                         \
            int col = nbase + nt * 8 + g;                                        \
            bf[nt][0] = __float_as_uint((dB)[col * PAS + k0]);                   \
            bf[nt][1] = __float_as_uint((dB)[col * PAS + k0 + 4]);               \
        }                                                                        \
        _Pragma("unroll")                                                        \
        for (int mt = 0; mt < 2; mt++)                                           \
            _Pragma("unroll")                                                    \
            for (int nt = 0; nt < 4; nt++)                                       \
                mma_tf32(ACC[mt][nt], a[mt], bf[nt]);                            \
    }                                                                            \
} while (0)

// ---------------- attention: 256 thr, M-split, cp.async pipeline ----------------
__global__ __launch_bounds__(256, 2) void attn_mma_kernel(
    const float* __restrict__ o1, const float* __restrict__ o2,
    const float* __restrict__ o1t, const float* __restrict__ o2t,
    const float* __restrict__ n1h, const float* __restrict__ n2h,
    const float* __restrict__ n1w, const float* __restrict__ n2w,
    const float* __restrict__ pbh, const float* __restrict__ pbw,
    float* __restrict__ attn1, float* __restrict__ attn2)
{
    extern __shared__ float sm[];
    const uint32_t sbase = (uint32_t)__cvta_generic_to_shared(sm);
    const int bh = blockIdx.x;
    const int mode = blockIdx.y;
    const int mh = blockIdx.z;
    const int hd = bh & 7, b = bh >> 3;
    const int tid = threadIdx.x;
    const int lane = tid & 31, g = lane >> 2, tig = lane & 3;
    const int wid = tid >> 5;
    const int mbase = (wid & 1) * 32;
    const int nbase = (wid >> 1) * 32;
    const int mh64 = mh * 64;
    const float* Abase = ((mode ? o1t : o2) + ((size_t)b * C_ + hd * CPH_) * HW_) + mh64 * 128;
    const float* Bbase = (mode ? o2t : o1) + ((size_t)b * C_ + hd * CPH_) * HW_;

    float acc[2][4][4];
#pragma unroll
    for (int mt = 0; mt < 2; mt++)
#pragma unroll
        for (int nt = 0; nt < 4; nt++)
#pragma unroll
            for (int e = 0; e < 4; e++) acc[mt][nt][e] = 0.f;

    PIPE_STAGE(sbase, Abase, Bbase);
    for (int kc = 0; kc < 48; kc++) {
        if (kc < 47) {
            int kn = kc + 1;
            const float* Ap = Abase + (kn >> 1) * HW_ + (kn & 1) * 64;
            const float* Bp = Bbase + (kn >> 1) * HW_ + (kn & 1) * 64;
            uint32_t sbuf = sbase + ((kn & 1) * PBUF) * 4;
            PIPE_STAGE(sbuf, Ap, Bp);
            CP_WAIT1();
        } else {
            CP_WAIT0();
        }
        __syncthreads();
        const float* dA = sm + (kc & 1) * PBUF;
        const float* dB = dA + AB_A;
        PIPE_MMA(dA, dB, acc);
        __syncthreads();
    }

    const float* nI = mode ? n1w : n2h;
    const float* nJ = mode ? n2w : n1h;
    const float bias = mode ? __ldg(&pbw[hd]) : __ldg(&pbh[hd]);
    float rinv[4], cinv[8];
#pragma unroll
    for (int mt = 0; mt < 2; mt++)
#pragma unroll
        for (int half = 0; half < 2; half++) {
            int row = mbase + mt * 16 + g + half * 8;
            rinv[mt * 2 + half] = TEMP_INV / fmaxf(__ldg(&nI[bh * 128 + mh64 + row]), EPS_);
        }
#pragma unroll
    for (int nt = 0; nt < 4; nt++)
#pragma unroll
        for (int cc = 0; cc < 2; cc++) {
            int col = nbase + nt * 8 + 2 * tig + cc;
            cinv[nt * 2 + cc] = 1.f / fmaxf(__ldg(&nJ[bh * 128 + col]), EPS_);
        }
    float* sc = sm;
#pragma unroll
    for (int mt = 0; mt < 2; mt++)
#pragma unroll
        for (int half = 0; half < 2; half++) {
            int row = mbase + mt * 16 + g + half * 8;
            float ri = rinv[mt * 2 + half];
#pragma unroll
            for (int nt = 0; nt < 4; nt++) {
                int col = nbase + nt * 8 + 2 * tig;
                float2 v;
                v.x = acc[mt][nt][half * 2 + 0] * (ri * cinv[nt * 2 + 0]) + bias;
                v.y = acc[mt][nt][half * 2 + 1] * (ri * cinv[nt * 2 + 1]) + bias;
                *(float2*)&sc[row * 132 + col] = v;
            }
        }
    __syncthreads();

    float* outp = (mode ? attn2 : attn1) + (size_t)bh * HW_ + mh64 * 128;
    for (int r = wid; r < 64; r += 8) {
        float4 v = *(float4*)&sc[r * 132 + lane * 4];
        float m = fmaxf(fmaxf(v.x, v.y), fmaxf(v.z, v.w));
#pragma unroll
        for (int s = 16; s >= 1; s >>= 1) m = fmaxf(m, __shfl_xor_sync(0xffffffffu, m, s));
        v.x = __expf(v.x - m); v.y = __expf(v.y - m);
        v.z = __expf(v.z - m); v.w = __expf(v.w - m);
        float su = v.x + v.y + v.z + v.w;
#pragma unroll
        for (int s = 16; s >= 1; s >>= 1) su += __shfl_xor_sync(0xffffffffu, su, s);
        float inv = 1.f / su;
        v.x *= inv; v.y *= inv; v.z *= inv; v.w *= inv;
        *(float4*)&outp[r * 128 + lane * 4] = to_tf32_4(v);
    }
}

// ---------------- AV + q-residual + gated fusion: 256 thr, M-split, cp.async ----------------
__global__ __launch_bounds__(256, 2) void av_mma_kernel(
    const float* __restrict__ o1, const float* __restrict__ o2,
    const float* __restrict__ o1t,
    const float* __restrict__ attn1, const float* __restrict__ attn2,
    const float* __restrict__ n2h, const float* __restrict__ n1w,
    const float* __restrict__ gate, float* __restrict__ fus)
{
    extern __shared__ float sm[];
    const uint32_t sbase = (uint32_t)__cvta_generic_to_shared(sm);
    const int ch = blockIdx.x, b = blockIdx.y;
    const int mh = blockIdx.z;
    const int hd = ch / CPH_;
    const int bh = b * 8 + hd;
    const int tid = threadIdx.x;
    const int lane = tid & 31, g = lane >> 2, tig = lane & 3;
    const int wid = tid >> 5;
    const int mbase = (wid & 1) * 32;
    const int nbase = (wid >> 1) * 32;
    const int mh64 = mh * 64;

    const float* A1 = attn1 + (size_t)bh * HW_ + mh64 * 128;
    const float* B1 = o1t + ((size_t)b * C_ + ch) * HW_;
    const float* A2 = o2 + ((size_t)b * C_ + ch) * HW_ + mh64 * 128;
    const float* B2 = attn2 + (size_t)bh * HW_;
    const float* S1 = o1 + ((size_t)b * C_ + ch) * HW_;
    const float* S2 = o2 + ((size_t)b * C_ + ch) * HW_;

    float acc1[2][4][4], acc2[2][4][4];
#pragma unroll
    for (int mt = 0; mt < 2; mt++)
#pragma unroll
        for (int nt = 0; nt < 4; nt++)
#pragma unroll
            for (int e = 0; e < 4; e++) { acc1[mt][nt][e] = 0.f; acc2[mt][nt][e] = 0.f; }

    const uint32_t sb0 = sbase;
    const uint32_t sb1 = sbase + PBUF * 4;
    const float* dA0 = sm;
    const float* dB0 = sm + AB_A;
    const float* dA1 = sm + PBUF;
    const float* dB1 = sm + PBUF + AB_A;

    PIPE_STAGE(sb0, A1, B1);
    PIPE_STAGE(sb1, A1 + 64, B1 + 64);
    CP_WAIT1(); __syncthreads();
    PIPE_MMA(dA0, dB0, acc1);
    __syncthreads();
    PIPE_STAGE(sb0, A2, B2);
    CP_WAIT1(); __syncthreads();
    PIPE_MMA(dA1, dB1, acc1);
    __syncthreads();
    PIPE_STAGE(sb1, A2 + 64, B2 + 64);
    CP_WAIT1(); __syncthreads();
    PIPE_MMA(dA0, dB0, acc2);
    CP_WAIT0(); __syncthreads();
    PIPE_MMA(dA1, dB1, acc2);

    const float gg = 1.f / (1.f + expf(-__ldg(&gate[0])));
    float invy[4], invx[8];
#pragma unroll
    for (int mt = 0; mt < 2; mt++)
#pragma unroll
        for (int half = 0; half < 2; half++) {
            int row = mbase + mt * 16 + g + half * 8;
            invy[mt * 2 + half] = 1.f / fmaxf(__ldg(&n2h[bh * 128 + mh64 + row]), EPS_);
        }
#pragma unroll
    for (int nt = 0; nt < 4; nt++)
#pragma unroll
        for (int cc = 0; cc < 2; cc++) {
            int col = nbase + nt * 8 + 2 * tig + cc;
            invx[nt * 2 + cc] = 1.f / fmaxf(__ldg(&n1w[bh * 128 + col]), EPS_);
        }

    float* fout = fus + ((size_t)b * C_ + ch) * HW_;
#pragma unroll
    for (int mt = 0; mt < 2; mt++)
#pragma unroll
        for (int half = 0; half < 2; half++) {
            int rl = mbase + mt * 16 + g + half * 8;
            int row = mh64 + rl;
            float iy = invy[mt * 2 + half];
#pragma unroll
            for (int nt = 0; nt < 4; nt++) {
                int col = nbase + nt * 8 + 2 * tig;
                float2 s1v = *(const float2*)(S1 + row * 128 + col);
                float2 s2v = *(const float2*)(S2 + row * 128 + col);
                float2 o;
                o.x = gg * (acc1[mt][nt][half * 2 + 0] + s2v.x * iy)
                    + (1.f - gg) * (acc2[mt][nt][half * 2 + 0] + s1v.x * invx[nt * 2 + 0]);
                o.y = gg * (acc1[mt][nt][half * 2 + 1] + s2v.y * iy)
                    + (1.f - gg) * (acc2[mt][nt][half * 2 + 1] + s1v.y * invx[nt * 2 + 1]);
                *(float2*)(fout + row * 128 + col) = o;
            }
        }
}

// ---------------- host launcher ----------------
extern "C" void kernel_launch(void* const* d_in, const int* in_sizes, int n_in,
                              void* d_out, int out_size)
{
    const float* x1  = (const float*)d_in[0];
    const float* x2  = (const float*)d_in[1];
    const float* Wp  = (const float*)d_in[2];
    const float* bp  = (const float*)d_in[3];
    const float* gate= (const float*)d_in[4];
    const float* pbh = (const float*)d_in[5];
    const float* pbw = (const float*)d_in[6];
    const float* Wm1 = (const float*)d_in[7];
    const float* bm1 = (const float*)d_in[8];
    const float* Wm2 = (const float*)d_in[9];
    const float* bm2 = (const float*)d_in[10];
    float* out = (float*)d_out;

    float *p_o1, *p_o2, *p_o1t, *p_o2t, *p_fus, *p_a1, *p_a2;
    float *p_n1h, *p_n2h, *p_n1w, *p_n2w;
    cudaGetSymbolAddress((void**)&p_o1, g_o1);
    cudaGetSymbolAddress((void**)&p_o2, g_o2);
    cudaGetSymbolAddress((void**)&p_o1t, g_o1t);
    cudaGetSymbolAddress((void**)&p_o2t, g_o2t);
    cudaGetSymbolAddress((void**)&p_fus, g_fus);
    cudaGetSymbolAddress((void**)&p_a1, g_attn1);
    cudaGetSymbolAddress((void**)&p_a2, g_attn2);
    cudaGetSymbolAddress((void**)&p_n1h, g_n1h);
    cudaGetSymbolAddress((void**)&p_n2h, g_n2h);
    cudaGetSymbolAddress((void**)&p_n1w, g_n1w);
    cudaGetSymbolAddress((void**)&p_n2w, g_n2w);

    cudaFuncSetAttribute(conv_front_kernel, cudaFuncAttributeMaxDynamicSharedMemorySize, SMEM_BYTES);
    cudaFuncSetAttribute(conv3x_kernel, cudaFuncAttributeMaxDynamicSharedMemorySize, C3_SMEM_BYTES);
    cudaFuncSetAttribute(attn_mma_kernel, cudaFuncAttributeMaxDynamicSharedMemorySize, PIPE_SMEM_BYTES);
    cudaFuncSetAttribute(av_mma_kernel, cudaFuncAttributeMaxDynamicSharedMemorySize, PIPE_SMEM_BYTES);

    // out1 = conv(x1), out2 = conv(x2) — channel-first in & out, one launch
    conv_front_kernel<<<dim3(NTILES_, 2), 512, SMEM_BYTES>>>(x1, x2, Wp, bp, p_o1, p_o2);

    // repack + fused norms (both sources in one launch)
    norm_init_kernel<<<32, 256>>>(p_n1h, p_n1w, p_n2h, p_n2w);
    repack_norm_kernel<<<dim3(16, 2 * C_, B_), dim3(32, 8)>>>(
        p_o1, p_o2, p_o1t, p_o2t, p_n1h, p_n1w, p_n2h, p_n2w);
    norm_fin_kernel<<<32, 256>>>(p_n1h, p_n1w, p_n2h, p_n2w);

    attn_mma_kernel<<<dim3(B_ * HEADS_, 2, 2), 256, PIPE_SMEM_BYTES>>>(
        p_o1, p_o2, p_o1t, p_o2t, p_n1h, p_n2h, p_n1w, p_n2w, pbh, pbw, p_a1, p_a2);

    av_mma_kernel<<<dim3(C_, B_, 2), 256, PIPE_SMEM_BYTES>>>(
        p_o1, p_o2, p_o1t, p_a1, p_a2, p_n2h, p_n1w, gate, p_fus);

    // fused tail: conv(Wp) -> gelu(conv(Wm1)) -> conv(Wm2) + x1 + x2
    conv3x_kernel<<<NTILES_, 512, C3_SMEM_BYTES>>>(p_fus, Wp, bp, Wm1, bm1, Wm2, bm2,
                                                   x1, x2, out);

    (void)in_sizes; (void)n_in; (void)out_size;
}

// round 12
// speedup vs baseline: 2.3831x; 1.1431x over previous
#include <cuda_runtime.h>
#include <cuda_bf16.h>
#include <math.h>
#include <stdint.h>

#define B_ 8
#define C_ 192
#define H_ 128
#define W_ 128
#define HW_ 16384
#define HEADS_ 8
#define CPH_ 24
#define TEMP_INV 100.0f
#define EPS_ 1e-12f

#define NPIX_ (B_ * HW_)
#define NTILES_ (NPIX_ / 128)

// ---------------- scratch ----------------
__device__ float g_o1[(size_t)B_ * C_ * HW_];
__device__ float g_o2[(size_t)B_ * C_ * HW_];
__device__ float g_fus[(size_t)B_ * C_ * HW_];
__device__ __nv_bfloat16 g_o1b[(size_t)B_ * C_ * HW_];   // [y][x] bf16
__device__ __nv_bfloat16 g_o2b[(size_t)B_ * C_ * HW_];
__device__ __nv_bfloat16 g_o1tb[(size_t)B_ * C_ * HW_];  // [x][y] bf16
__device__ __nv_bfloat16 g_o2tb[(size_t)B_ * C_ * HW_];
__device__ __nv_bfloat16 g_a1b[(size_t)B_ * HEADS_ * HW_];
__device__ __nv_bfloat16 g_a2b[(size_t)B_ * HEADS_ * HW_];
__device__ float g_n1h[B_ * HEADS_ * H_];
__device__ float g_n2h[B_ * HEADS_ * H_];
__device__ float g_n1w[B_ * HEADS_ * W_];
__device__ float g_n2w[B_ * HEADS_ * W_];

__device__ __forceinline__ float to_tf32(float x) {
    uint32_t u; asm("cvt.rna.tf32.f32 %0, %1;" : "=r"(u) : "f"(x));
    return __uint_as_float(u);
}
__device__ __forceinline__ float4 to_tf32_4(float4 v) {
    v.x = to_tf32(v.x); v.y = to_tf32(v.y); v.z = to_tf32(v.z); v.w = to_tf32(v.w);
    return v;
}
__device__ __forceinline__ uint32_t f2bf2(float a, float b) {
    __nv_bfloat162 h = __floats2bfloat162_rn(a, b);
    return *(uint32_t*)&h;
}

__device__ __forceinline__ void mma_tf32(float* c, const uint32_t* a, const uint32_t* b) {
    asm volatile(
        "mma.sync.aligned.m16n8k8.row.col.f32.tf32.tf32.f32 "
        "{%0,%1,%2,%3}, {%4,%5,%6,%7}, {%8,%9}, {%0,%1,%2,%3};"
        : "+f"(c[0]), "+f"(c[1]), "+f"(c[2]), "+f"(c[3])
        : "r"(a[0]), "r"(a[1]), "r"(a[2]), "r"(a[3]), "r"(b[0]), "r"(b[1]));
}
__device__ __forceinline__ void mma_bf16(float* c, const uint32_t* a, const uint32_t* b) {
    asm volatile(
        "mma.sync.aligned.m16n8k16.row.col.f32.bf16.bf16.f32 "
        "{%0,%1,%2,%3}, {%4,%5,%6,%7}, {%8,%9}, {%0,%1,%2,%3};"
        : "+f"(c[0]), "+f"(c[1]), "+f"(c[2]), "+f"(c[3])
        : "r"(a[0]), "r"(a[1]), "r"(a[2]), "r"(a[3]), "r"(b[0]), "r"(b[1]));
}

__device__ __forceinline__ void cpa16(uint32_t s, const void* g) {
    asm volatile("cp.async.cg.shared.global [%0], [%1], 16;" :: "r"(s), "l"(g));
}
#define CP_COMMIT() asm volatile("cp.async.commit_group;" ::: "memory")
#define CP_WAIT1()  asm volatile("cp.async.wait_group 1;" ::: "memory")
#define CP_WAIT0()  asm volatile("cp.async.wait_group 0;" ::: "memory")

// ---------------- repack + norms + bf16 operand emission ----------------
__global__ __launch_bounds__(256) void repack_norm_kernel(
    const float* __restrict__ o1, const float* __restrict__ o2,
    __nv_bfloat16* __restrict__ o1b, __nv_bfloat16* __restrict__ o2b,
    __nv_bfloat16* __restrict__ o1tb, __nv_bfloat16* __restrict__ o2tb,
    float* __restrict__ n1h, float* __restrict__ n1w,
    float* __restrict__ n2h, float* __restrict__ n2w)
{
    __shared__ float t[32][33];
    __shared__ float cpart[8][32];
    const int cy = blockIdx.y;
    const int src = cy >= C_;
    const int c = src ? cy - C_ : cy;
    const int b = blockIdx.z;
    const int bh = b * 8 + c / CPH_;
    const int x0 = (blockIdx.x & 3) * 32, y0 = (blockIdx.x >> 2) * 32;
    const int tx = threadIdx.x, ty = threadIdx.y;
    const float* ib = (src ? o2 : o1) + ((size_t)b * C_ + c) * HW_;
    __nv_bfloat16* obr = (src ? o2b : o1b) + ((size_t)b * C_ + c) * HW_;
    __nv_bfloat16* obt = (src ? o2tb : o1tb) + ((size_t)b * C_ + c) * HW_;
    float* rowAcc = (src ? n2h : n1h);
    float* colAcc = (src ? n2w : n1w);

    float colLoc = 0.f;
#pragma unroll
    for (int ii = 0; ii < 4; ii++) {
        int i = ty + 8 * ii;
        float v = ib[(y0 + i) * 128 + x0 + tx];
        t[i][tx] = v;
        obr[(y0 + i) * 128 + x0 + tx] = __float2bfloat16_rn(v);
        float sq = v * v;
        colLoc += sq;
        float rs = sq;
#pragma unroll
        for (int s = 16; s >= 1; s >>= 1) rs += __shfl_xor_sync(0xffffffffu, rs, s);
        if (tx == 0) atomicAdd(&rowAcc[bh * 128 + y0 + i], rs);
    }
    cpart[ty][tx] = colLoc;
    __syncthreads();
#pragma unroll
    for (int i = ty; i < 32; i += 8)
        obt[(x0 + i) * 128 + y0 + tx] = __float2bfloat16_rn(t[tx][i]);
    if (ty == 0) {
        float s = cpart[0][tx] + cpart[1][tx] + cpart[2][tx] + cpart[3][tx]
                + cpart[4][tx] + cpart[5][tx] + cpart[6][tx] + cpart[7][tx];
        atomicAdd(&colAcc[bh * 128 + x0 + tx], s);
    }
}

__global__ void norm_init_kernel(float* a, float* b, float* c, float* d) {
    int i = blockIdx.x * 256 + threadIdx.x;
    if (i < B_ * HEADS_ * 128) { a[i] = 0.f; b[i] = 0.f; c[i] = 0.f; d[i] = 0.f; }
}
__global__ void norm_fin_kernel(float* a, float* b, float* c, float* d) {
    int i = blockIdx.x * 256 + threadIdx.x;
    if (i < B_ * HEADS_ * 128) {
        a[i] = sqrtf(a[i]); b[i] = sqrtf(b[i]); c[i] = sqrtf(c[i]); d[i] = sqrtf(d[i]);
    }
}

// ---------------- conv1x1 from channel-first input via mma.sync tf32 ----------------
#define SAS 36
#define ATS 136
#define CONV_ATBUF (32 * ATS)
#define CONV_WBUF (192 * SAS)
#define SMEM_BYTES ((2 * CONV_ATBUF + 2 * CONV_WBUF) * 4)

__global__ __launch_bounds__(512, 1) void conv_front_kernel(
    const float* __restrict__ x1, const float* __restrict__ x2,
    const float* __restrict__ Wt, const float* __restrict__ bias,
    float* __restrict__ o1, float* __restrict__ o2)
{
    extern __shared__ float sm[];
    const int tid = threadIdx.x;
    const int lane = tid & 31;
    const int g = lane >> 2;
    const int tig = lane & 3;
    const int wid = tid >> 5;
    const int mbase = (wid & 3) * 32;
    const int nbase = (wid >> 2) * 48;
    const int t = blockIdx.x;
    const int pg0 = t << 7;
    const int b = pg0 >> 14;
    const int p0 = pg0 & (HW_ - 1);
    const float* inb = (blockIdx.y ? x2 : x1) + (size_t)b * C_ * HW_;
    float* out = (blockIdx.y ? o2 : o1);

    float c[2][6][4];
#pragma unroll
    for (int mt = 0; mt < 2; mt++)
#pragma unroll
        for (int nt = 0; nt < 6; nt++)
#pragma unroll
            for (int r = 0; r < 4; r++) c[mt][nt][r] = 0.f;

    float4 pa[2], pw[3];
#pragma unroll
    for (int r = 0; r < 2; r++) {
        int f = tid + 512 * r;
        pa[r] = *(const float4*)(inb + (size_t)(f >> 5) * HW_ + p0 + (f & 31) * 4);
    }
#pragma unroll
    for (int r = 0; r < 3; r++) {
        int f = tid + 512 * r;
        pw[r] = *(const float4*)(Wt + (size_t)(f >> 3) * C_ + (f & 7) * 4);
    }

    for (int kc = 0; kc < 6; kc++) {
        float* dA = sm + (kc & 1) * CONV_ATBUF;
        float* dW = sm + 2 * CONV_ATBUF + (kc & 1) * CONV_WBUF;
#pragma unroll
        for (int r = 0; r < 2; r++) {
            int f = tid + 512 * r;
            *(float4*)&dA[(f >> 5) * ATS + (f & 31) * 4] = to_tf32_4(pa[r]);
        }
#pragma unroll
        for (int r = 0; r < 3; r++) {
            int f = tid + 512 * r;
            *(float4*)&dW[(f >> 3) * SAS + (f & 7) * 4] = to_tf32_4(pw[r]);
        }
        __syncthreads();
        if (kc < 5) {
            int ko = (kc + 1) * 32;
#pragma unroll
            for (int r = 0; r < 2; r++) {
                int f = tid + 512 * r;
                pa[r] = *(const float4*)(inb + (size_t)(ko + (f >> 5)) * HW_ + p0 + (f & 31) * 4);
            }
#pragma unroll
            for (int r = 0; r < 3; r++) {
                int f = tid + 512 * r;
                pw[r] = *(const float4*)(Wt + (size_t)(f >> 3) * C_ + ko + (f & 7) * 4);
            }
        }
#pragma unroll
        for (int kk = 0; kk < 4; kk++) {
            const int k0 = kk * 8 + tig;
            uint32_t a[2][4], bb[6][2];
#pragma unroll
            for (int mt = 0; mt < 2; mt++) {
                int row = mbase + mt * 16 + g;
                a[mt][0] = __float_as_uint(dA[k0 * ATS + row]);
                a[mt][1] = __float_as_uint(dA[k0 * ATS + row + 8]);
                a[mt][2] = __float_as_uint(dA[(k0 + 4) * ATS + row]);
                a[mt][3] = __float_as_uint(dA[(k0 + 4) * ATS + row + 8]);
            }
#pragma unroll
            for (int nt = 0; nt < 6; nt++) {
                int col = nbase + nt * 8 + g;
                bb[nt][0] = __float_as_uint(dW[col * SAS + k0]);
                bb[nt][1] = __float_as_uint(dW[col * SAS + k0 + 4]);
            }
#pragma unroll
            for (int mt = 0; mt < 2; mt++)
#pragma unroll
                for (int nt = 0; nt < 6; nt++)
                    mma_tf32(c[mt][nt], a[mt], bb[nt]);
        }
    }

#pragma unroll
    for (int nt = 0; nt < 6; nt++) {
        int o = nbase + nt * 8 + 2 * tig;
        float bv0 = __ldg(&bias[o]);
        float bv1 = __ldg(&bias[o + 1]);
#pragma unroll
        for (int mt = 0; mt < 2; mt++)
#pragma unroll
            for (int half = 0; half < 2; half++) {
                int row = mbase + mt * 16 + g + half * 8;
#pragma unroll
                for (int cc = 0; cc < 2; cc++) {
                    float v = c[mt][nt][half * 2 + cc] + (cc ? bv1 : bv0);
                    out[((size_t)(b * C_ + o + cc) << 14) + p0 + row] = to_tf32(v);
                }
            }
    }
}

// ---------------- fused triple conv ----------------
#define C3_SO_STRIDE 196
#define C3_SO_FLOATS (128 * C3_SO_STRIDE)
#define C3_W_OFF C3_SO_FLOATS
#define C3_SMEM_BYTES ((C3_SO_FLOATS + 2 * CONV_WBUF) * 4)

#define C3_MMALOOP_SO(kbase, dWpt, ACC) do {                                     \
    _Pragma("unroll")                                                            \
    for (int kk = 0; kk < 4; kk++) {                                             \
        const int k0 = kk * 8 + tig;                                             \
        uint32_t a[2][4], bb[6][2];                                              \
        _Pragma("unroll")                                                        \
        for (int mt = 0; mt < 2; mt++) {                                         \
            int row = mbase + mt * 16 + g;                                       \
            a[mt][0] = __float_as_uint(sO[row * C3_SO_STRIDE + (kbase) + k0]);   \
            a[mt][1] = __float_as_uint(sO[(row + 8) * C3_SO_STRIDE + (kbase) + k0]); \
            a[mt][2] = __float_as_uint(sO[row * C3_SO_STRIDE + (kbase) + k0 + 4]); \
            a[mt][3] = __float_as_uint(sO[(row + 8) * C3_SO_STRIDE + (kbase) + k0 + 4]); \
        }                                                                        \
        _Pragma("unroll")                                                        \
        for (int nt = 0; nt < 6; nt++) {                                         \
            int col = nbase + nt * 8 + g;                                        \
            bb[nt][0] = __float_as_uint((dWpt)[col * SAS + k0]);                 \
            bb[nt][1] = __float_as_uint((dWpt)[col * SAS + k0 + 4]);             \
        }                                                                        \
        _Pragma("unroll")                                                        \
        for (int mt = 0; mt < 2; mt++)                                           \
            _Pragma("unroll")                                                    \
            for (int nt = 0; nt < 6; nt++)                                       \
                mma_tf32(ACC[mt][nt], a[mt], bb[nt]);                            \
    }                                                                            \
} while (0)

#define C3_LOADW(Wsrc, ko) do {                                                  \
    _Pragma("unroll")                                                            \
    for (int r = 0; r < 3; r++) {                                                \
        int f = tid + 512 * r;                                                   \
        pw[r] = *(const float4*)((Wsrc) + (size_t)(f >> 3) * C_ + (ko) + (f & 7) * 4); \
    }                                                                            \
} while (0)

#define C3_STOREW(dWpt) do {                                                     \
    _Pragma("unroll")                                                            \
    for (int r = 0; r < 3; r++) {                                                \
        int f = tid + 512 * r;                                                   \
        *(float4*)&(dWpt)[(f >> 3) * SAS + (f & 7) * 4] = to_tf32_4(pw[r]);      \
    }                                                                            \
} while (0)

#define C3_ZEROACC(ACC) do {                                                     \
    _Pragma("unroll")                                                            \
    for (int mt = 0; mt < 2; mt++)                                               \
        _Pragma("unroll")                                                        \
        for (int nt = 0; nt < 6; nt++)                                           \
            _Pragma("unroll")                                                    \
            for (int r = 0; r < 4; r++) ACC[mt][nt][r] = 0.f;                    \
} while (0)

#define C3_EPI_SMEM(ACC, biasp, do_gelu) do {                                    \
    _Pragma("unroll")                                                            \
    for (int nt = 0; nt < 6; nt++) {                                             \
        int o = nbase + nt * 8 + 2 * tig;                                        \
        float bv0 = __ldg(&(biasp)[o]);                                          \
        float bv1 = __ldg(&(biasp)[o + 1]);                                      \
        _Pragma("unroll")                                                        \
        for (int mt = 0; mt < 2; mt++)                                           \
            _Pragma("unroll")                                                    \
            for (int half = 0; half < 2; half++) {                               \
                int row = mbase + mt * 16 + g + half * 8;                        \
                float v0 = ACC[mt][nt][half * 2 + 0] + bv0;                      \
                float v1 = ACC[mt][nt][half * 2 + 1] + bv1;                      \
                if (do_gelu) {                                                   \
                    v0 = 0.5f * v0 * (1.0f + erff(v0 * 0.70710678118654752f));   \
                    v1 = 0.5f * v1 * (1.0f + erff(v1 * 0.70710678118654752f));   \
                }                                                                \
                float2 w = {to_tf32(v0), to_tf32(v1)};                           \
                *(float2*)&sO[row * C3_SO_STRIDE + o] = w;                       \
            }                                                                    \
    }                                                                            \
} while (0)

__global__ __launch_bounds__(512, 1) void conv3x_kernel(
    const float* __restrict__ fus,
    const float* __restrict__ Wp,  const float* __restrict__ bp,
    const float* __restrict__ Wm1, const float* __restrict__ bm1,
    const float* __restrict__ Wm2, const float* __restrict__ bm2,
    const float* __restrict__ r1,  const float* __restrict__ r2,
    float* __restrict__ out)
{
    extern __shared__ float sm[];
    float* sO = sm;
    float* sW = sm + C3_W_OFF;
    const int tid = threadIdx.x;
    const int lane = tid & 31;
    const int g = lane >> 2;
    const int tig = lane & 3;
    const int wid = tid >> 5;
    const int mbase = (wid & 3) * 32;
    const int nbase = (wid >> 2) * 48;
    const int t = blockIdx.x;
    const int pg0 = t << 7;
    const int b = pg0 >> 14;
    const int p0 = pg0 & (HW_ - 1);
    const float* inb = fus + (size_t)b * C_ * HW_;

    float acc[2][6][4];
    float4 pa[2], pw[3];

    C3_ZEROACC(acc);
#pragma unroll
    for (int r = 0; r < 2; r++) {
        int f = tid + 512 * r;
        pa[r] = *(const float4*)(inb + (size_t)(f >> 5) * HW_ + p0 + (f & 31) * 4);
    }
    C3_LOADW(Wp, 0);
    for (int kc = 0; kc < 6; kc++) {
        float* dA = sm + (kc & 1) * CONV_ATBUF;
        float* dW = sW + (kc & 1) * CONV_WBUF;
#pragma unroll
        for (int r = 0; r < 2; r++) {
            int f = tid + 512 * r;
            *(float4*)&dA[(f >> 5) * ATS + (f & 31) * 4] = to_tf32_4(pa[r]);
        }
        C3_STOREW(dW);
        __syncthreads();
        if (kc < 5) {
            int ko = (kc + 1) * 32;
#pragma unroll
            for (int r = 0; r < 2; r++) {
                int f = tid + 512 * r;
                pa[r] = *(const float4*)(inb + (size_t)(ko + (f >> 5)) * HW_ + p0 + (f & 31) * 4);
            }
            C3_LOADW(Wp, ko);
        }
#pragma unroll
        for (int kk = 0; kk < 4; kk++) {
            const int k0 = kk * 8 + tig;
            uint32_t a[2][4], bb[6][2];
#pragma unroll
            for (int mt = 0; mt < 2; mt++) {
                int row = mbase + mt * 16 + g;
                a[mt][0] = __float_as_uint(dA[k0 * ATS + row]);
                a[mt][1] = __float_as_uint(dA[k0 * ATS + row + 8]);
                a[mt][2] = __float_as_uint(dA[(k0 + 4) * ATS + row]);
                a[mt][3] = __float_as_uint(dA[(k0 + 4) * ATS + row + 8]);
            }
#pragma unroll
            for (int nt = 0; nt < 6; nt++) {
                int col = nbase + nt * 8 + g;
                bb[nt][0] = __float_as_uint(dW[col * SAS + k0]);
                bb[nt][1] = __float_as_uint(dW[col * SAS + k0 + 4]);
            }
#pragma unroll
            for (int mt = 0; mt < 2; mt++)
#pragma unroll
                for (int nt = 0; nt < 6; nt++)
                    mma_tf32(acc[mt][nt], a[mt], bb[nt]);
        }
    }
    __syncthreads();
    C3_EPI_SMEM(acc, bp, 0);
    __syncthreads();

    C3_ZEROACC(acc);
    C3_LOADW(Wm1, 0);
    for (int kc = 0; kc < 6; kc++) {
        float* dW = sW + (kc & 1) * CONV_WBUF;
        C3_STOREW(dW);
        __syncthreads();
        if (kc < 5) C3_LOADW(Wm1, (kc + 1) * 32);
        C3_MMALOOP_SO(kc * 32, dW, acc);
    }
    __syncthreads();
    C3_EPI_SMEM(acc, bm1, 1);
    __syncthreads();

    C3_ZEROACC(acc);
    C3_LOADW(Wm2, 0);
    for (int kc = 0; kc < 6; kc++) {
        float* dW = sW + (kc & 1) * CONV_WBUF;
        C3_STOREW(dW);
        __syncthreads();
        if (kc < 5) C3_LOADW(Wm2, (kc + 1) * 32);
        C3_MMALOOP_SO(kc * 32, dW, acc);
    }

#pragma unroll
    for (int nt = 0; nt < 6; nt++) {
        int o = nbase + nt * 8 + 2 * tig;
        float bv0 = __ldg(&bm2[o]);
        float bv1 = __ldg(&bm2[o + 1]);
#pragma unroll
        for (int mt = 0; mt < 2; mt++)
#pragma unroll
            for (int half = 0; half < 2; half++) {
                int row = mbase + mt * 16 + g + half * 8;
#pragma unroll
                for (int cc = 0; cc < 2; cc++) {
                    float v = acc[mt][nt][half * 2 + cc] + (cc ? bv1 : bv0);
                    size_t idx = ((size_t)(b * C_ + o + cc) << 14) + p0 + row;
                    v += __ldg(&r1[idx]) + __ldg(&r2[idx]);
                    out[idx] = v;
                }
            }
    }
}

// ---------------- bf16 pipeline constants (attn/av, 256 thr, M-split 64) ----------------
// K-chunk 64 bf16 = 32 u32 per row (8 x 16B chunks), row stride 36 u32
#define BPAS 36
#define BAB_A (64 * BPAS)       // 2304 u32
#define BAB_B (128 * BPAS)      // 4608 u32
#define BPBUF (BAB_A + BAB_B)   // 6912 u32
#define BPIPE_SMEM_BYTES (2 * BPBUF * 4)   // 55296

// stage: A 64 rows x 8 chunks (2 iters), B 128 rows x 8 chunks (4 iters)
#define BPIPE_STAGE(sbuf32, Ap, Bp) do {                                         \
    _Pragma("unroll")                                                            \
    for (int r = 0; r < 2; r++) {                                                \
        int f = tid + 256 * r;                                                   \
        int row = f >> 3, c8 = f & 7;                                            \
        cpa16((sbuf32) + (row * BPAS + c8 * 4) * 4, (Ap) + row * 128 + c8 * 8);  \
    }                                                                            \
    _Pragma("unroll")                                                            \
    for (int r = 0; r < 4; r++) {                                                \
        int f = tid + 256 * r;                                                   \
        int row = f >> 3, c8 = f & 7;                                            \
        cpa16((sbuf32) + (BAB_A + row * BPAS + c8 * 4) * 4, (Bp) + row * 128 + c8 * 8); \
    }                                                                            \
    CP_COMMIT();                                                                 \
} while (0)

#define BPIPE_MMA(dA, dB, ACC) do {                                              \
    _Pragma("unroll")                                                            \
    for (int w = 0; w < 4; w++) {                                                \
        const int kp = w * 8 + tig;                                              \
        uint32_t a[2][4], bf[4][2];                                              \
        _Pragma("unroll")                                                        \
        for (int mt = 0; mt < 2; mt++) {                                         \
            int row = mbase + mt * 16 + g;                                       \
            a[mt][0] = (dA)[row * BPAS + kp];                                    \
            a[mt][1] = (dA)[(row + 8) * BPAS + kp];                              \
            a[mt][2] = (dA)[row * BPAS + kp + 4];                                \
            a[mt][3] = (dA)[(row + 8) * BPAS + kp + 4];                          \
        }                                                                        \
        _Pragma("unroll")                                                        \
        for (int nt = 0; nt < 4; nt++) {                                         \
            int col = nbase + nt * 8 + g;                                        \
            bf[nt][0] = (dB)[col * BPAS + kp];                                   \
            bf[nt][1] = (dB)[col * BPAS + kp + 4];                               \
        }                                                                        \
        _Pragma("unroll")                                                        \
        for (int mt = 0; mt < 2; mt++)                                           \
            _Pragma("unroll")                                                    \
            for (int nt = 0; nt < 4; nt++)                                       \
                mma_bf16(ACC[mt][nt], a[mt], bf[nt]);                            \
    }                                                                            \
} while (0)

// ---------------- attention: bf16 operands, fused softmax, bf16 output ----------------
__global__ __launch_bounds__(256, 2) void attn_mma_kernel(
    const __nv_bfloat16* __restrict__ o1b, const __nv_bfloat16* __restrict__ o2b,
    const __nv_bfloat16* __restrict__ o1tb, const __nv_bfloat16* __restrict__ o2tb,
    const float* __restrict__ n1h, const float* __restrict__ n2h,
    const float* __restrict__ n1w, const float* __restrict__ n2w,
    const float* __restrict__ pbh, const float* __restrict__ pbw,
    __nv_bfloat16* __restrict__ a1b, __nv_bfloat16* __restrict__ a2b)
{
    extern __shared__ float smf[];
    uint32_t* smu = (uint32_t*)smf;
    const uint32_t sbase = (uint32_t)__cvta_generic_to_shared(smf);
    const int bh = blockIdx.x;
    const int mode = blockIdx.y;
    const int mh = blockIdx.z;
    const int hd = bh & 7, b = bh >> 3;
    const int tid = threadIdx.x;
    const int lane = tid & 31, g = lane >> 2, tig = lane & 3;
    const int wid = tid >> 5;
    const int mbase = (wid & 1) * 32;
    const int nbase = (wid >> 1) * 32;
    const int mh64 = mh * 64;
    const __nv_bfloat16* Abase =
        ((mode ? o1tb : o2b) + ((size_t)b * C_ + hd * CPH_) * HW_) + mh64 * 128;
    const __nv_bfloat16* Bbase = (mode ? o2tb : o1b) + ((size_t)b * C_ + hd * CPH_) * HW_;

    float acc[2][4][4];
#pragma unroll
    for (int mt = 0; mt < 2; mt++)
#pragma unroll
        for (int nt = 0; nt < 4; nt++)
#pragma unroll
            for (int e = 0; e < 4; e++) acc[mt][nt][e] = 0.f;

    BPIPE_STAGE(sbase, Abase, Bbase);
    for (int kc = 0; kc < 48; kc++) {
        if (kc < 47) {
            int kn = kc + 1;
            const __nv_bfloat16* Ap = Abase + (kn >> 1) * HW_ + (kn & 1) * 64;
            const __nv_bfloat16* Bp = Bbase + (kn >> 1) * HW_ + (kn & 1) * 64;
            uint32_t sbuf = sbase + ((kn & 1) * BPBUF) * 4;
            BPIPE_STAGE(sbuf, Ap, Bp);
            CP_WAIT1();
        } else {
            CP_WAIT0();
        }
        __syncthreads();
        const uint32_t* dA = smu + (kc & 1) * BPBUF;
        const uint32_t* dB = dA + BAB_A;
        BPIPE_MMA(dA, dB, acc);
        __syncthreads();
    }

    const float* nI = mode ? n1w : n2h;
    const float* nJ = mode ? n2w : n1h;
    const float bias = mode ? __ldg(&pbw[hd]) : __ldg(&pbh[hd]);
    float rinv[4], cinv[8];
#pragma unroll
    for (int mt = 0; mt < 2; mt++)
#pragma unroll
        for (int half = 0; half < 2; half++) {
            int row = mbase + mt * 16 + g + half * 8;
            rinv[mt * 2 + half] = TEMP_INV / fmaxf(__ldg(&nI[bh * 128 + mh64 + row]), EPS_);
        }
#pragma unroll
    for (int nt = 0; nt < 4; nt++)
#pragma unroll
        for (int cc = 0; cc < 2; cc++) {
            int col = nbase + nt * 8 + 2 * tig + cc;
            cinv[nt * 2 + cc] = 1.f / fmaxf(__ldg(&nJ[bh * 128 + col]), EPS_);
        }
    float* sc = smf;   // 64 x 132 logits (33792 B < 55296)
#pragma unroll
    for (int mt = 0; mt < 2; mt++)
#pragma unroll
        for (int half = 0; half < 2; half++) {
            int row = mbase + mt * 16 + g + half * 8;
            float ri = rinv[mt * 2 + half];
#pragma unroll
            for (int nt = 0; nt < 4; nt++) {
                int col = nbase + nt * 8 + 2 * tig;
                float2 v;
                v.x = acc[mt][nt][half * 2 + 0] * (ri * cinv[nt * 2 + 0]) + bias;
                v.y = acc[mt][nt][half * 2 + 1] * (ri * cinv[nt * 2 + 1]) + bias;
                *(float2*)&sc[row * 132 + col] = v;
            }
        }
    __syncthreads();

    __nv_bfloat16* outp = (mode ? a2b : a1b) + (size_t)bh * HW_ + mh64 * 128;
    for (int r = wid; r < 64; r += 8) {
        float4 v = *(float4*)&sc[r * 132 + lane * 4];
        float m = fmaxf(fmaxf(v.x, v.y), fmaxf(v.z, v.w));
#pragma unroll
        for (int s = 16; s >= 1; s >>= 1) m = fmaxf(m, __shfl_xor_sync(0xffffffffu, m, s));
        v.x = __expf(v.x - m); v.y = __expf(v.y - m);
        v.z = __expf(v.z - m); v.w = __expf(v.w - m);
        float su = v.x + v.y + v.z + v.w;
#pragma unroll
        for (int s = 16; s >= 1; s >>= 1) su += __shfl_xor_sync(0xffffffffu, su, s);
        float inv = 1.f / su;
        uint2 o;
        o.x = f2bf2(v.x * inv, v.y * inv);
        o.y = f2bf2(v.z * inv, v.w * inv);
        *(uint2*)&outp[r * 128 + lane * 4] = o;
    }
}

// ---------------- AV + q-residual + gated fusion: bf16 GEMMs ----------------
__global__ __launch_bounds__(256, 2) void av_mma_kernel(
    const float* __restrict__ o1, const float* __restrict__ o2,
    const __nv_bfloat16* __restrict__ o1tb, const __nv_bfloat16* __restrict__ o2b,
    const __nv_bfloat16* __restrict__ a1b, const __nv_bfloat16* __restrict__ a2b,
    const float* __restrict__ n2h, const float* __restrict__ n1w,
    const float* __restrict__ gate, float* __restrict__ fus)
{
    extern __shared__ float smf[];
    uint32_t* smu = (uint32_t*)smf;
    const uint32_t sbase = (uint32_t)__cvta_generic_to_shared(smf);
    const int ch = blockIdx.x, b = blockIdx.y;
    const int mh = blockIdx.z;
    const int hd = ch / CPH_;
    const int bh = b * 8 + hd;
    const int tid = threadIdx.x;
    const int lane = tid & 31, g = lane >> 2, tig = lane & 3;
    const int wid = tid >> 5;
    const int mbase = (wid & 1) * 32;
    const int nbase = (wid >> 1) * 32;
    const int mh64 = mh * 64;

    const __nv_bfloat16* A1 = a1b + (size_t)bh * HW_ + mh64 * 128;
    const __nv_bfloat16* B1 = o1tb + ((size_t)b * C_ + ch) * HW_;
    const __nv_bfloat16* A2 = o2b + ((size_t)b * C_ + ch) * HW_ + mh64 * 128;
    const __nv_bfloat16* B2 = a2b + (size_t)bh * HW_;
    const float* S1 = o1 + ((size_t)b * C_ + ch) * HW_;
    const float* S2 = o2 + ((size_t)b * C_ + ch) * HW_;

    float acc1[2][4][4], acc2[2][4][4];
#pragma unroll
    for (int mt = 0; mt < 2; mt++)
#pragma unroll
        for (int nt = 0; nt < 4; nt++)
#pragma unroll
            for (int e = 0; e < 4; e++) { acc1[mt][nt][e] = 0.f; acc2[mt][nt][e] = 0.f; }

    const uint32_t sb0 = sbase;
    const uint32_t sb1 = sbase + BPBUF * 4;
    const uint32_t* dA0 = smu;
    const uint32_t* dB0 = smu + BAB_A;
    const uint32_t* dA1 = smu + BPBUF;
    const uint32_t* dB1 = smu + BPBUF + BAB_A;

    BPIPE_STAGE(sb0, A1, B1);
    BPIPE_STAGE(sb1, A1 + 64, B1 + 64);
    CP_WAIT1(); __syncthreads();
    BPIPE_MMA(dA0, dB0, acc1);
    __syncthreads();
    BPIPE_STAGE(sb0, A2, B2);
    CP_WAIT1(); __syncthreads();
    BPIPE_MMA(dA1, dB1, acc1);
    __syncthreads();
    BPIPE_STAGE(sb1, A2 + 64, B2 + 64);
    CP_WAIT1(); __syncthreads();
    BPIPE_MMA(dA0, dB0, acc2);
    CP_WAIT0(); __syncthreads();
    BPIPE_MMA(dA1, dB1, acc2);

    const float gg = 1.f / (1.f + expf(-__ldg(&gate[0])));
    float invy[4], invx[8];
#pragma unroll
    for (int mt = 0; mt < 2; mt++)
#pragma unroll
        for (int half = 0; half < 2; half++) {
            int row = mbase + mt * 16 + g + half * 8;
            invy[mt * 2 + half] = 1.f / fmaxf(__ldg(&n2h[bh * 128 + mh64 + row]), EPS_);
        }
#pragma unroll
    for (int nt = 0; nt < 4; nt++)
#pragma unroll
        for (int cc = 0; cc < 2; cc++) {
            int col = nbase + nt * 8 + 2 * tig + cc;
            invx[nt * 2 + cc] = 1.f / fmaxf(__ldg(&n1w[bh * 128 + col]), EPS_);
        }

    float* fout = fus + ((size_t)b * C_ + ch) * HW_;
#pragma unroll
    for (int mt = 0; mt < 2; mt++)
#pragma unroll
        for (int half = 0; half < 2; half++) {
            int rl = mbase + mt * 16 + g + half * 8;
            int row = mh64 + rl;
            float iy = invy[mt * 2 + half];
#pragma unroll
            for (int nt = 0; nt < 4; nt++) {
                int col = nbase + nt * 8 + 2 * tig;
                float2 s1v = *(const float2*)(S1 + row * 128 + col);
                float2 s2v = *(const float2*)(S2 + row * 128 + col);
                float2 o;
                o.x = gg * (acc1[mt][nt][half * 2 + 0] + s2v.x * iy)
                    + (1.f - gg) * (acc2[mt][nt][half * 2 + 0] + s1v.x * invx[nt * 2 + 0]);
                o.y = gg * (acc1[mt][nt][half * 2 + 1] + s2v.y * iy)
                    + (1.f - gg) * (acc2[mt][nt][half * 2 + 1] + s1v.y * invx[nt * 2 + 1]);
                *(float2*)(fout + row * 128 + col) = o;
            }
        }
}

// ---------------- host launcher ----------------
extern "C" void kernel_launch(void* const* d_in, const int* in_sizes, int n_in,
                              void* d_out, int out_size)
{
    const float* x1  = (const float*)d_in[0];
    const float* x2  = (const float*)d_in[1];
    const float* Wp  = (const float*)d_in[2];
    const float* bp  = (const float*)d_in[3];
    const float* gate= (const float*)d_in[4];
    const float* pbh = (const float*)d_in[5];
    const float* pbw = (const float*)d_in[6];
    const float* Wm1 = (const float*)d_in[7];
    const float* bm1 = (const float*)d_in[8];
    const float* Wm2 = (const float*)d_in[9];
    const float* bm2 = (const float*)d_in[10];
    float* out = (float*)d_out;

    float *p_o1, *p_o2, *p_fus, *p_n1h, *p_n2h, *p_n1w, *p_n2w;
    __nv_bfloat16 *p_o1b, *p_o2b, *p_o1tb, *p_o2tb, *p_a1b, *p_a2b;
    cudaGetSymbolAddress((void**)&p_o1, g_o1);
    cudaGetSymbolAddress((void**)&p_o2, g_o2);
    cudaGetSymbolAddress((void**)&p_fus, g_fus);
    cudaGetSymbolAddress((void**)&p_o1b, g_o1b);
    cudaGetSymbolAddress((void**)&p_o2b, g_o2b);
    cudaGetSymbolAddress((void**)&p_o1tb, g_o1tb);
    cudaGetSymbolAddress((void**)&p_o2tb, g_o2tb);
    cudaGetSymbolAddress((void**)&p_a1b, g_a1b);
    cudaGetSymbolAddress((void**)&p_a2b, g_a2b);
    cudaGetSymbolAddress((void**)&p_n1h, g_n1h);
    cudaGetSymbolAddress((void**)&p_n2h, g_n2h);
    cudaGetSymbolAddress((void**)&p_n1w, g_n1w);
    cudaGetSymbolAddress((void**)&p_n2w, g_n2w);

    cudaFuncSetAttribute(conv_front_kernel, cudaFuncAttributeMaxDynamicSharedMemorySize, SMEM_BYTES);
    cudaFuncSetAttribute(conv3x_kernel, cudaFuncAttributeMaxDynamicSharedMemorySize, C3_SMEM_BYTES);
    cudaFuncSetAttribute(attn_mma_kernel, cudaFuncAttributeMaxDynamicSharedMemorySize, BPIPE_SMEM_BYTES);
    cudaFuncSetAttribute(av_mma_kernel, cudaFuncAttributeMaxDynamicSharedMemorySize, BPIPE_SMEM_BYTES);

    conv_front_kernel<<<dim3(NTILES_, 2), 512, SMEM_BYTES>>>(x1, x2, Wp, bp, p_o1, p_o2);

    norm_init_kernel<<<32, 256>>>(p_n1h, p_n1w, p_n2h, p_n2w);
    repack_norm_kernel<<<dim3(16, 2 * C_, B_), dim3(32, 8)>>>(
        p_o1, p_o2, p_o1b, p_o2b, p_o1tb, p_o2tb, p_n1h, p_n1w, p_n2h, p_n2w);
    norm_fin_kernel<<<32, 256>>>(p_n1h, p_n1w, p_n2h, p_n2w);

    attn_mma_kernel<<<dim3(B_ * HEADS_, 2, 2), 256, BPIPE_SMEM_BYTES>>>(
        p_o1b, p_o2b, p_o1tb, p_o2tb, p_n1h, p_n2h, p_n1w, p_n2w, pbh, pbw, p_a1b, p_a2b);

    av_mma_kernel<<<dim3(C_, B_, 2), 256, BPIPE_SMEM_BYTES>>>(
        p_o1, p_o2, p_o1tb, p_o2b, p_a1b, p_a2b, p_n2h, p_n1w, gate, p_fus);

    conv3x_kernel<<<NTILES_, 512, C3_SMEM_BYTES>>>(p_fus, Wp, bp, Wm1, bm1, Wm2, bm2,
                                                   x1, x2, out);

    (void)in_sizes; (void)n_in; (void)out_size;
}